// round 5
// baseline (speedup 1.0000x reference)
#include <cuda_runtime.h>
#include <cuda_bf16.h>
#include <math.h>
#include <stdint.h>

// ---------------- problem constants ----------------
#define LSEQ 512
#define BB   8
#define EE   1024
#define HH   16
#define HD   64
#define NLAY 2
#define DFF  4096
#define MROWS (LSEQ*BB)          // 4096
#define BHN  (BB*HH)             // 128
#define QSZ  ((size_t)BHN*LSEQ*HD)   // elements per Q/K/V tensor

// ---------------- scratch (device globals) ----------------
__device__ float4 g_pt4  [(size_t)LSEQ*LSEQ*HD/4];     // pos+typ (rounded) [L,L,HD]
__device__ float4 g_qkvs4[(size_t)3*QSZ/4];            // Q|K|V  [bh,l,d] rounded
__device__ float4 g_S4   [(size_t)BHN*LSEQ*LSEQ/4];    // [bh, l, s]
__device__ float4 g_AO4  [(size_t)BHN*LSEQ*HD/4];      // attn out [bh,l,d]
__device__ float4 g_AL4  [(size_t)MROWS*EE/4];         // attn out [l,b,e] rounded
__device__ float4 g_Y4   [(size_t)MROWS*EE/4];
__device__ float4 g_X14  [(size_t)MROWS*EE/4];         // exact LN1 out
__device__ float4 g_X1r4 [(size_t)MROWS*EE/4];         // rounded LN1 out
__device__ float4 g_X4   [(size_t)MROWS*EE/4];         // exact layer out
__device__ float4 g_Xr4  [(size_t)MROWS*EE/4];         // rounded layer out / src
__device__ float4 g_H4   [(size_t)MROWS*DFF/4];        // ffn hidden (rounded)
// rounded weights
__device__ float4 g_Wir4 [(size_t)NLAY*3*EE*EE/4];
__device__ float4 g_Wor4 [(size_t)NLAY*EE*EE/4];
__device__ float4 g_W1r4 [(size_t)NLAY*DFF*EE/4];
__device__ float4 g_W2r4 [(size_t)NLAY*EE*DFF/4];

__device__ __forceinline__ float gelu_exact(float x) {
    return 0.5f * x * (1.0f + erff(x * 0.70710678118654752f));
}
__device__ __forceinline__ uint32_t f2tf(float x) {
    uint32_t u;
    asm("cvt.rna.tf32.f32 %0, %1;" : "=r"(u) : "f"(x));
    return u;
}
__device__ __forceinline__ float rndtf(float x) { return __uint_as_float(f2tf(x)); }

__device__ __forceinline__ void cp16(uint32_t saddr, const void* gaddr) {
    asm volatile("cp.async.cg.shared.global [%0], [%1], 16;\n"
                 :: "r"(saddr), "l"(gaddr));
}
__device__ __forceinline__ void cp_commit() {
    asm volatile("cp.async.commit_group;\n");
}
template<int N>
__device__ __forceinline__ void cp_wait() {
    asm volatile("cp.async.wait_group %0;\n" :: "n"(N));
}

// ---------------- TF32 tensor-core GEMM, cp.async 3-stage, 1 sync/iter ----------------
// Inputs assumed pre-rounded to TF32 (RNA) in gmem.
// EPI: 0 none; 1 +bias; 2 +bias,gelu,round; 3 qkv-split epilogue (bias, q-scale,
//      round, scatter to aux as Q|K|V [bh,l,d]); 4 accum-from-C + round + scatter
//      to aux as [l,b,e] (l = blockIdx.z).
template<int BM, int BN, int WM, int WN, bool TRANSB, int EPI, bool ACCUM>
__global__ void __launch_bounds__((BM/WM)*(BN/WN)*32, 2)
tgemm(const float* __restrict__ A, int lda, long long sAz,
      const float* __restrict__ B, int ldb, long long sBz,
      float* __restrict__ C, int ldc, long long sCz,
      const float* __restrict__ bias, float* __restrict__ aux,
      int M, int N, int K)
{
    constexpr int BK = 32;
    constexpr int WARPS_M = BM / WM;
    constexpr int WARPS_N = BN / WN;
    constexpr int THREADS = WARPS_M * WARPS_N * 32;
    constexpr int LDSA = BK + 4;                       // 36
    constexpr int LDSB = TRANSB ? (BK + 4) : (BN + 8);
    constexpr int A_WORDS = BM * LDSA;
    constexpr int B_WORDS = TRANSB ? (BN * LDSA) : (BK * LDSB);
    constexpr int STAGE_WORDS = A_WORDS + B_WORDS;
    constexpr int NSTAGE = 3;
    constexpr int MI = WM / 16;
    constexpr int NI = WN / 8;

    extern __shared__ uint32_t smem[];

    A += (long long)blockIdx.z * sAz;
    B += (long long)blockIdx.z * sBz;
    C += (long long)blockIdx.z * sCz;

    const int bm = blockIdx.y * BM;
    const int bn = blockIdx.x * BN;
    const int tid  = threadIdx.x;
    const int wid  = tid >> 5;
    const int lane = tid & 31;
    const int wm = (wid / WARPS_N) * WM;
    const int wn = (wid % WARPS_N) * WN;
    const int g = lane >> 2;
    const int c = lane & 3;

    uint32_t smem_base;
    asm("{ .reg .u64 t; cvta.to.shared.u64 t, %1; cvt.u32.u64 %0, t; }"
        : "=r"(smem_base) : "l"(smem));

    float acc[MI][NI][4];
    #pragma unroll
    for (int mi = 0; mi < MI; mi++)
        #pragma unroll
        for (int ni = 0; ni < NI; ni++)
            #pragma unroll
            for (int r = 0; r < 4; r++) acc[mi][ni][r] = 0.f;

    const int nIter = K / BK;

    auto load_tiles = [&](int stage, int k0) {
        uint32_t sA = smem_base + (uint32_t)(stage * STAGE_WORDS) * 4u;
        uint32_t sB = sA + (uint32_t)A_WORDS * 4u;
        #pragma unroll
        for (int i = tid; i < BM * (BK/4); i += THREADS) {
            int row = i / (BK/4);
            int kc  = (i % (BK/4)) * 4;
            cp16(sA + (uint32_t)(row * LDSA + kc) * 4u,
                 A + (size_t)(bm + row) * lda + k0 + kc);
        }
        if (TRANSB) {
            #pragma unroll
            for (int i = tid; i < BN * (BK/4); i += THREADS) {
                int row = i / (BK/4);
                int kc  = (i % (BK/4)) * 4;
                cp16(sB + (uint32_t)(row * LDSA + kc) * 4u,
                     B + (size_t)(bn + row) * ldb + k0 + kc);
            }
        } else {
            #pragma unroll
            for (int i = tid; i < BK * (BN/4); i += THREADS) {
                int kk  = i / (BN/4);
                int col = (i % (BN/4)) * 4;
                cp16(sB + (uint32_t)(kk * LDSB + col) * 4u,
                     B + (size_t)(k0 + kk) * ldb + bn + col);
            }
        }
        cp_commit();
    };

    load_tiles(0, 0);
    if (nIter > 1) load_tiles(1, BK);

    for (int it = 0; it < nIter; it++) {
        if (it + 2 < nIter) { cp_wait<1>(); } else { cp_wait<0>(); }
        __syncthreads();
        if (it + 2 < nIter) load_tiles((it + 2) % NSTAGE, (it + 2) * BK);

        const uint32_t* As = smem + (it % NSTAGE) * STAGE_WORDS;
        const uint32_t* Bs = As + A_WORDS;

        #pragma unroll
        for (int kk = 0; kk < BK; kk += 8) {
            uint32_t af[MI][4], bf[NI][2];
            #pragma unroll
            for (int mi = 0; mi < MI; mi++) {
                const uint32_t* p0 = &As[(wm + mi*16 + g) * LDSA + kk + c];
                const uint32_t* p1 = &As[(wm + mi*16 + g + 8) * LDSA + kk + c];
                af[mi][0] = p0[0]; af[mi][2] = p0[4];
                af[mi][1] = p1[0]; af[mi][3] = p1[4];
            }
            #pragma unroll
            for (int ni = 0; ni < NI; ni++) {
                if (TRANSB) {
                    const uint32_t* p = &Bs[(wn + ni*8 + g) * LDSA + kk + c];
                    bf[ni][0] = p[0]; bf[ni][1] = p[4];
                } else {
                    bf[ni][0] = Bs[(kk + c)     * LDSB + wn + ni*8 + g];
                    bf[ni][1] = Bs[(kk + c + 4) * LDSB + wn + ni*8 + g];
                }
            }
            #pragma unroll
            for (int mi = 0; mi < MI; mi++)
                #pragma unroll
                for (int ni = 0; ni < NI; ni++) {
                    asm volatile(
                        "mma.sync.aligned.m16n8k8.row.col.f32.tf32.tf32.f32 "
                        "{%0,%1,%2,%3}, {%4,%5,%6,%7}, {%8,%9}, {%0,%1,%2,%3};\n"
                        : "+f"(acc[mi][ni][0]), "+f"(acc[mi][ni][1]),
                          "+f"(acc[mi][ni][2]), "+f"(acc[mi][ni][3])
                        : "r"(af[mi][0]), "r"(af[mi][1]),
                          "r"(af[mi][2]), "r"(af[mi][3]),
                          "r"(bf[ni][0]), "r"(bf[ni][1]));
                }
        }
    }

    // ---- epilogue ----
    #pragma unroll
    for (int mi = 0; mi < MI; mi++) {
        #pragma unroll
        for (int ni = 0; ni < NI; ni++) {
            int row = bm + wm + mi*16 + g;
            int col = bn + wn + ni*8 + 2*c;
            float bx = 0.f, by = 0.f;
            if (EPI == 1 || EPI == 2 || EPI == 3) { bx = bias[col]; by = bias[col+1]; }
            #pragma unroll
            for (int half = 0; half < 2; half++) {
                int r = row + half*8;
                float vx = acc[mi][ni][half*2+0];
                float vy = acc[mi][ni][half*2+1];
                if (EPI == 1 || EPI == 2 || EPI == 3) { vx += bx; vy += by; }
                if (EPI == 2) {
                    vx = rndtf(gelu_exact(vx)); vy = rndtf(gelu_exact(vy));
                }
                if (EPI == 3) {
                    // qkv split: row = l*8+b, col in [0,3E)
                    int l = r >> 3, b = r & 7;
                    int which = col >> 10;
                    int e = col & 1023;
                    int h = e >> 6, d = e & 63;
                    int bh = b * HH + h;
                    if (which == 0) { vx *= 0.125f; vy *= 0.125f; }
                    vx = rndtf(vx); vy = rndtf(vy);
                    float2* P = (float2*)(aux + (size_t)which * QSZ
                                          + ((size_t)bh * LSEQ + l) * HD + d);
                    *P = make_float2(vx, vy);
                    continue;
                }
                if (EPI == 4) {
                    // accum from C (AO layout), round, scatter to [l,b,e]
                    float2 o = *(float2*)(C + (size_t)r * ldc + col);
                    int l = blockIdx.z;
                    int b = r >> 4, h = r & 15;   // r = bh
                    float2* P = (float2*)(aux + ((size_t)(l * BB + b) * EE)
                                          + h * HD + col);
                    *P = make_float2(rndtf(vx + o.x), rndtf(vy + o.y));
                    continue;
                }
                float2* Cp = (float2*)(C + (size_t)r * ldc + col);
                if (ACCUM) {
                    float2 o = *Cp;
                    vx += o.x; vy += o.y;
                }
                *Cp = make_float2(vx, vy);
            }
        }
    }
}

// ---------------- elementwise rounded add (pt = round(pos + typ)) ----------------
__global__ void add2r_kernel(const float4* __restrict__ a, const float4* __restrict__ b,
                             float4* __restrict__ o, int n4)
{
    int i = blockIdx.x * blockDim.x + threadIdx.x;
    if (i < n4) {
        float4 x = a[i], y = b[i];
        o[i] = make_float4(rndtf(x.x+y.x), rndtf(x.y+y.y),
                           rndtf(x.z+y.z), rndtf(x.w+y.w));
    }
}

// ---------------- elementwise tf32-round ----------------
__global__ void round4_kernel(const float4* __restrict__ a, float4* __restrict__ o, int n4)
{
    int i = blockIdx.x * blockDim.x + threadIdx.x;
    if (i < n4) {
        float4 x = a[i];
        o[i] = make_float4(rndtf(x.x), rndtf(x.y), rndtf(x.z), rndtf(x.w));
    }
}

// ---------------- softmax over rows of 512 (warp per row), rounded store ----------------
__global__ void softmax512_kernel(float* __restrict__ S)
{
    long long row = (long long)blockIdx.x * 8 + threadIdx.y;
    float* p = S + row * LSEQ;
    int lane = threadIdx.x;
    float v[16];
    float mx = -1e30f;
    #pragma unroll
    for (int i = 0; i < 16; i++) { v[i] = p[i*32 + lane]; mx = fmaxf(mx, v[i]); }
    #pragma unroll
    for (int o = 16; o; o >>= 1) mx = fmaxf(mx, __shfl_xor_sync(0xffffffffu, mx, o));
    float s = 0.f;
    #pragma unroll
    for (int i = 0; i < 16; i++) { v[i] = __expf(v[i] - mx); s += v[i]; }
    #pragma unroll
    for (int o = 16; o; o >>= 1) s += __shfl_xor_sync(0xffffffffu, s, o);
    float inv = 1.0f / s;
    #pragma unroll
    for (int i = 0; i < 16; i++) p[i*32 + lane] = rndtf(v[i] * inv);
}

// ---------------- LN(residual); exact out + optional rounded copy ----------------
__global__ void ln_res_kernel(const float* __restrict__ X, const float* __restrict__ Y,
                              const float* __restrict__ g, const float* __restrict__ be,
                              float* __restrict__ O, float* __restrict__ Or)
{
    int row = blockIdx.x;
    int t = threadIdx.x;      // 256 threads, 1 float4 each
    const float4* x4 = (const float4*)(X + (size_t)row * EE);
    const float4* y4 = (const float4*)(Y + (size_t)row * EE);
    float4 a = x4[t], b = y4[t];
    float4 v = make_float4(a.x+b.x, a.y+b.y, a.z+b.z, a.w+b.w);
    float s = v.x + v.y + v.z + v.w;
    float q = v.x*v.x + v.y*v.y + v.z*v.z + v.w*v.w;
    __shared__ float sh_s[8], sh_q[8];
    #pragma unroll
    for (int o = 16; o; o >>= 1) {
        s += __shfl_xor_sync(0xffffffffu, s, o);
        q += __shfl_xor_sync(0xffffffffu, q, o);
    }
    int wid = t >> 5, lane = t & 31;
    if (!lane) { sh_s[wid] = s; sh_q[wid] = q; }
    __syncthreads();
    if (t < 32) {
        s = (lane < 8) ? sh_s[lane] : 0.f;
        q = (lane < 8) ? sh_q[lane] : 0.f;
        #pragma unroll
        for (int o = 4; o; o >>= 1) {
            s += __shfl_xor_sync(0xffffffffu, s, o);
            q += __shfl_xor_sync(0xffffffffu, q, o);
        }
        if (!lane) { sh_s[0] = s; sh_q[0] = q; }
    }
    __syncthreads();
    float mean = sh_s[0] * (1.f/EE);
    float var  = sh_q[0] * (1.f/EE) - mean * mean;
    float r = rsqrtf(var + 1e-5f);
    float4 gg = ((const float4*)g)[t];
    float4 bb = ((const float4*)be)[t];
    float4 o;
    o.x = (v.x - mean) * r * gg.x + bb.x;
    o.y = (v.y - mean) * r * gg.y + bb.y;
    o.z = (v.z - mean) * r * gg.z + bb.z;
    o.w = (v.w - mean) * r * gg.w + bb.w;
    ((float4*)(O + (size_t)row * EE))[t] = o;
    if (Or) {
        float4 orr = make_float4(rndtf(o.x), rndtf(o.y), rndtf(o.z), rndtf(o.w));
        ((float4*)(Or + (size_t)row * EE))[t] = orr;
    }
}

// ---------------- launch ----------------
static float* sym(const void* devSymbol) {
    void* p = nullptr;
    cudaGetSymbolAddress(&p, devSymbol);
    return (float*)p;
}

#define SMEM_NT_128x128 (3 * (128*36 + 128*36) * 4)   // 110592
#define SMEM_NN_128x64  (3 * (128*36 + 32*72) * 4)    // 82944

extern "C" void kernel_launch(void* const* d_in, const int* in_sizes, int n_in,
                              void* d_out, int out_size)
{
    const float* src = (const float*)d_in[0];
    const float* pos = (const float*)d_in[1];
    const float* typ = (const float*)d_in[2];
    const float* Wi  = (const float*)d_in[3];
    const float* bi  = (const float*)d_in[4];
    const float* Wo  = (const float*)d_in[5];
    const float* bo  = (const float*)d_in[6];
    const float* W1  = (const float*)d_in[7];
    const float* b1  = (const float*)d_in[8];
    const float* W2  = (const float*)d_in[9];
    const float* b2  = (const float*)d_in[10];
    const float* g1  = (const float*)d_in[11];
    const float* be1 = (const float*)d_in[12];
    const float* g2  = (const float*)d_in[13];
    const float* be2 = (const float*)d_in[14];
    float* out = (float*)d_out;

    float* PT   = sym(g_pt4);
    float* QKVS = sym(g_qkvs4);          // Q | K | V
    float* Q = QKVS, *K = QKVS + QSZ, *V = QKVS + 2*QSZ;
    float* S   = sym(g_S4);
    float* AO  = sym(g_AO4);
    float* AL  = sym(g_AL4);
    float* Y   = sym(g_Y4);
    float* X1  = sym(g_X14);
    float* X1r = sym(g_X1r4);
    float* X   = sym(g_X4);
    float* Xr  = sym(g_Xr4);
    float* Hb  = sym(g_H4);
    float* Wir = sym(g_Wir4);
    float* Wor = sym(g_Wor4);
    float* W1r = sym(g_W1r4);
    float* W2r = sym(g_W2r4);

    static bool attrs_done = false;
    if (!attrs_done) {
        cudaFuncSetAttribute(tgemm<128,128,64,32,true,3,false>,
                             cudaFuncAttributeMaxDynamicSharedMemorySize, SMEM_NT_128x128);
        cudaFuncSetAttribute(tgemm<128,128,64,32,true,1,false>,
                             cudaFuncAttributeMaxDynamicSharedMemorySize, SMEM_NT_128x128);
        cudaFuncSetAttribute(tgemm<128,128,64,32,true,0,false>,
                             cudaFuncAttributeMaxDynamicSharedMemorySize, SMEM_NT_128x128);
        cudaFuncSetAttribute(tgemm<128,128,64,32,true,0,true>,
                             cudaFuncAttributeMaxDynamicSharedMemorySize, SMEM_NT_128x128);
        cudaFuncSetAttribute(tgemm<128,128,64,32,true,2,false>,
                             cudaFuncAttributeMaxDynamicSharedMemorySize, SMEM_NT_128x128);
        cudaFuncSetAttribute(tgemm<128,64,32,32,false,0,false>,
                             cudaFuncAttributeMaxDynamicSharedMemorySize, SMEM_NN_128x64);
        cudaFuncSetAttribute(tgemm<128,64,32,32,false,4,false>,
                             cudaFuncAttributeMaxDynamicSharedMemorySize, SMEM_NN_128x64);
        attrs_done = true;
    }

    // pre-round constant GEMM inputs (RNA tf32)
    add2r_kernel<<<16384, 256>>>((const float4*)pos, (const float4*)typ,
                                 (float4*)PT, 4194304);
    round4_kernel<<<(NLAY*3*EE*EE/4 + 255)/256, 256>>>((const float4*)Wi, (float4*)Wir, NLAY*3*EE*EE/4);
    round4_kernel<<<(NLAY*EE*EE/4   + 255)/256, 256>>>((const float4*)Wo, (float4*)Wor, NLAY*EE*EE/4);
    round4_kernel<<<(NLAY*DFF*EE/4  + 255)/256, 256>>>((const float4*)W1, (float4*)W1r, NLAY*DFF*EE/4);
    round4_kernel<<<(NLAY*EE*DFF/4  + 255)/256, 256>>>((const float4*)W2, (float4*)W2r, NLAY*EE*DFF/4);
    round4_kernel<<<(MROWS*EE/4     + 255)/256, 256>>>((const float4*)src, (float4*)Xr, MROWS*EE/4);

    const float* x = src;     // exact residual input
    for (int l = 0; l < NLAY; l++) {
        // 1) QKV GEMM + fused split/scale/round epilogue -> Q|K|V [bh,l,d]
        tgemm<128,128,64,32,true,3,false><<<dim3(24,32,1), 256, SMEM_NT_128x128>>>(
            Xr, EE, 0, Wir + (size_t)l*3*EE*EE, EE, 0,
            nullptr, 0, 0, bi + (size_t)l*3*EE, QKVS, MROWS, 3*EE, EE);

        // 2) scores = Q @ K^T  (batched over bh=128)  [512,512] K=64
        tgemm<128,128,64,32,true,0,false><<<dim3(4,4,BHN), 256, SMEM_NT_128x128>>>(
            Q, HD, (long long)LSEQ*HD, K, HD, (long long)LSEQ*HD,
            S, LSEQ, (long long)LSEQ*LSEQ, nullptr, nullptr, LSEQ, LSEQ, HD);

        // 3) scores[:,l,:] += Qf[l] @ pt[l]^T (batched over l=512) [128,512] K=64
        tgemm<128,128,64,32,true,0,true><<<dim3(4,1,LSEQ), 256, SMEM_NT_128x128>>>(
            Q, LSEQ*HD, (long long)HD,
            PT, HD, (long long)LSEQ*HD,
            S, LSEQ*LSEQ, (long long)LSEQ,
            nullptr, nullptr, BHN, LSEQ, HD);

        // 4) softmax rows (rounded store)
        softmax512_kernel<<<BHN*LSEQ/8, dim3(32,8)>>>(S);

        // 5) AO = W @ V (batched over bh)  [512,64] K=512, NN
        tgemm<128,64,32,32,false,0,false><<<dim3(1,4,BHN), 256, SMEM_NN_128x64>>>(
            S, LSEQ, (long long)LSEQ*LSEQ, V, HD, (long long)LSEQ*HD,
            AO, HD, (long long)LSEQ*HD, nullptr, nullptr, LSEQ, HD, LSEQ);

        // 6) AL[l,b,e] = round(AO + W_l @ pt[l]) (batched over l), fused reorder
        tgemm<128,64,32,32,false,4,false><<<dim3(1,1,LSEQ), 256, SMEM_NN_128x64>>>(
            S, LSEQ*LSEQ, (long long)LSEQ,
            PT, HD, (long long)LSEQ*HD,
            AO, LSEQ*HD, (long long)HD,
            nullptr, AL, BHN, HD, LSEQ);

        // 7) Y = AL @ Wor^T + bo   [4096,1024] K=1024
        tgemm<128,128,64,32,true,1,false><<<dim3(8,32,1), 256, SMEM_NT_128x128>>>(
            AL, EE, 0, Wor + (size_t)l*EE*EE, EE, 0,
            Y, EE, 0, bo + (size_t)l*EE, nullptr, MROWS, EE, EE);

        // 8) X1 = LN(x + Y)  (exact) + X1r (rounded)
        ln_res_kernel<<<MROWS, 256>>>(x, Y, g1 + (size_t)l*EE, be1 + (size_t)l*EE, X1, X1r);

        // 9) H = round(gelu(X1r @ W1r^T + b1))   [4096,4096] K=1024
        tgemm<128,128,64,32,true,2,false><<<dim3(32,32,1), 256, SMEM_NT_128x128>>>(
            X1r, EE, 0, W1r + (size_t)l*DFF*EE, EE, 0,
            Hb, DFF, 0, b1 + (size_t)l*DFF, nullptr, MROWS, DFF, EE);

        // 10) Y = H @ W2r^T + b2   [4096,1024] K=4096
        tgemm<128,128,64,32,true,1,false><<<dim3(8,32,1), 256, SMEM_NT_128x128>>>(
            Hb, DFF, 0, W2r + (size_t)l*EE*DFF, DFF, 0,
            Y, EE, 0, b2 + (size_t)l*EE, nullptr, MROWS, EE, DFF);

        // 11) next = LN(X1 + Y); last layer -> d_out (exact), else X + rounded Xr
        float* xo   = (l == NLAY-1) ? out : X;
        float* xor_ = (l == NLAY-1) ? nullptr : Xr;
        ln_res_kernel<<<MROWS, 256>>>(X1, Y, g2 + (size_t)l*EE, be2 + (size_t)l*EE, xo, xor_);

        x = X;
    }
}

// round 6
// speedup vs baseline: 1.3506x; 1.3506x over previous
#include <cuda_runtime.h>
#include <cuda_fp16.h>
#include <math.h>
#include <stdint.h>

// ---------------- problem constants ----------------
#define LSEQ 512
#define BB   8
#define EE   1024
#define HH   16
#define HD   64
#define NLAY 2
#define DFF  4096
#define MROWS (LSEQ*BB)          // 4096
#define BHN  (BB*HH)             // 128
#define QSZ  ((size_t)BHN*LSEQ*HD)
#define PT_ELEMS ((size_t)LSEQ*LSEQ*HD)

// ---------------- scratch (device globals, uint4 for 16B alignment) ----------------
__device__ uint4  g_PTh [PT_ELEMS/8];                 // pos+typ half [l,s,d]
__device__ uint4  g_PTt [PT_ELEMS/8];                 // pos+typ half [l,d,s]
__device__ uint4  g_QKVh[3*QSZ/8];                    // Q|K half [bh,l,d]; V half [bh,d,s]
__device__ float4 g_S4  [(size_t)BHN*LSEQ*LSEQ/4];    // scores fp32 [bh,l,s]
__device__ uint4  g_Wh  [(size_t)BHN*LSEQ*LSEQ/8];    // softmax weights half [bh,l,s]
__device__ float4 g_AO4 [(size_t)BHN*LSEQ*HD/4];      // attn out fp32 [bh,l,d]
__device__ uint4  g_ALh [(size_t)MROWS*EE/8];         // attn out half [l,b,e]
__device__ float4 g_Y4  [(size_t)MROWS*EE/4];
__device__ float4 g_X14 [(size_t)MROWS*EE/4];         // exact LN1 out
__device__ uint4  g_X1h [(size_t)MROWS*EE/8];         // half LN1 out
__device__ float4 g_X4  [(size_t)MROWS*EE/4];         // exact layer out
__device__ uint4  g_Xh  [(size_t)MROWS*EE/8];         // half layer in
__device__ uint4  g_Hh  [(size_t)MROWS*DFF/8];        // ffn hidden half
// half weights
__device__ uint4  g_Wih [(size_t)NLAY*3*EE*EE/8];
__device__ uint4  g_Woh [(size_t)NLAY*EE*EE/8];
__device__ uint4  g_W1h [(size_t)NLAY*DFF*EE/8];
__device__ uint4  g_W2h [(size_t)NLAY*EE*DFF/8];

__device__ __forceinline__ float gelu_exact(float x) {
    return 0.5f * x * (1.0f + erff(x * 0.70710678118654752f));
}

__device__ __forceinline__ void cp16(uint32_t saddr, const void* gaddr) {
    asm volatile("cp.async.cg.shared.global [%0], [%1], 16;\n"
                 :: "r"(saddr), "l"(gaddr));
}
__device__ __forceinline__ void cp_commit() {
    asm volatile("cp.async.commit_group;\n");
}
template<int N>
__device__ __forceinline__ void cp_wait() {
    asm volatile("cp.async.wait_group %0;\n" :: "n"(N));
}

// ---------------- FP16 tensor-core GEMM (NT only), cp.async 3-stage ----------------
// C[M,N] (+)= A[M,K] * B[N,K]^T, fp32 accumulate.
// EPI: 0 plain fp32 C (ACCUM optional); 1 +bias -> fp32 C;
//      2 +bias, gelu -> half auxh[r*ldc+col];
//      3 qkv split: +bias, (q*0.125), half -> Q|K [bh,l,d], V -> [bh,d,s] in auxh;
//      4 read fp32 C (AO), add, half -> auxh[(l*BB+b)*EE + h*HD + col], l=blockIdx.z.
template<int BM, int BN, int WM, int WN, int EPI, bool ACCUM>
__global__ void __launch_bounds__((BM/WM)*(BN/WN)*32, 2)
hgemm(const __half* __restrict__ A, int lda, long long sAz,
      const __half* __restrict__ B, int ldb, long long sBz,
      float* __restrict__ C, int ldc, long long sCz,
      const float* __restrict__ bias, __half* __restrict__ auxh,
      int M, int N, int K)
{
    constexpr int BK = 32;                  // halves in k per stage
    constexpr int WARPS_M = BM / WM;
    constexpr int WARPS_N = BN / WN;
    constexpr int THREADS = WARPS_M * WARPS_N * 32;
    constexpr int LDSA = BK + 8;            // 40 halves -> 80B rows: 16B-aligned, frag conflict-free
    constexpr int A_HALVES = BM * LDSA;
    constexpr int B_HALVES = BN * LDSA;
    constexpr int STAGE_HALVES = A_HALVES + B_HALVES;
    constexpr int NSTAGE = 3;
    constexpr int MI = WM / 16;
    constexpr int NI = WN / 8;

    extern __shared__ __half smem[];

    A += (long long)blockIdx.z * sAz;
    B += (long long)blockIdx.z * sBz;
    C += (long long)blockIdx.z * sCz;

    const int bm = blockIdx.y * BM;
    const int bn = blockIdx.x * BN;
    const int tid  = threadIdx.x;
    const int wid  = tid >> 5;
    const int lane = tid & 31;
    const int wm = (wid / WARPS_N) * WM;
    const int wn = (wid % WARPS_N) * WN;
    const int g = lane >> 2;
    const int c = lane & 3;

    uint32_t smem_base;
    asm("{ .reg .u64 t; cvta.to.shared.u64 t, %1; cvt.u32.u64 %0, t; }"
        : "=r"(smem_base) : "l"(smem));

    float acc[MI][NI][4];
    #pragma unroll
    for (int mi = 0; mi < MI; mi++)
        #pragma unroll
        for (int ni = 0; ni < NI; ni++)
            #pragma unroll
            for (int r = 0; r < 4; r++) acc[mi][ni][r] = 0.f;

    const int nIter = K / BK;

    auto load_tiles = [&](int stage, int k0) {
        uint32_t sA = smem_base + (uint32_t)(stage * STAGE_HALVES) * 2u;
        uint32_t sB = sA + (uint32_t)A_HALVES * 2u;
        #pragma unroll
        for (int i = tid; i < BM * (BK/8); i += THREADS) {
            int row = i / (BK/8);
            int kc  = (i % (BK/8)) * 8;
            cp16(sA + (uint32_t)(row * LDSA + kc) * 2u,
                 A + (size_t)(bm + row) * lda + k0 + kc);
        }
        #pragma unroll
        for (int i = tid; i < BN * (BK/8); i += THREADS) {
            int row = i / (BK/8);
            int kc  = (i % (BK/8)) * 8;
            cp16(sB + (uint32_t)(row * LDSA + kc) * 2u,
                 B + (size_t)(bn + row) * ldb + k0 + kc);
        }
        cp_commit();
    };

    load_tiles(0, 0);
    if (nIter > 1) load_tiles(1, BK);

    for (int it = 0; it < nIter; it++) {
        if (it + 2 < nIter) { cp_wait<1>(); } else { cp_wait<0>(); }
        __syncthreads();
        if (it + 2 < nIter) load_tiles((it + 2) % NSTAGE, (it + 2) * BK);

        const __half* As = smem + (it % NSTAGE) * STAGE_HALVES;
        const __half* Bs = As + A_HALVES;

        #pragma unroll
        for (int kk = 0; kk < BK; kk += 16) {
            uint32_t af[MI][4], bf[NI][2];
            #pragma unroll
            for (int mi = 0; mi < MI; mi++) {
                const __half* p0 = As + (wm + mi*16 + g)     * LDSA + kk + 2*c;
                const __half* p1 = As + (wm + mi*16 + g + 8) * LDSA + kk + 2*c;
                af[mi][0] = *(const uint32_t*)p0;
                af[mi][1] = *(const uint32_t*)p1;
                af[mi][2] = *(const uint32_t*)(p0 + 8);
                af[mi][3] = *(const uint32_t*)(p1 + 8);
            }
            #pragma unroll
            for (int ni = 0; ni < NI; ni++) {
                const __half* p = Bs + (wn + ni*8 + g) * LDSA + kk + 2*c;
                bf[ni][0] = *(const uint32_t*)p;
                bf[ni][1] = *(const uint32_t*)(p + 8);
            }
            #pragma unroll
            for (int mi = 0; mi < MI; mi++)
                #pragma unroll
                for (int ni = 0; ni < NI; ni++) {
                    asm volatile(
                        "mma.sync.aligned.m16n8k16.row.col.f32.f16.f16.f32 "
                        "{%0,%1,%2,%3}, {%4,%5,%6,%7}, {%8,%9}, {%0,%1,%2,%3};\n"
                        : "+f"(acc[mi][ni][0]), "+f"(acc[mi][ni][1]),
                          "+f"(acc[mi][ni][2]), "+f"(acc[mi][ni][3])
                        : "r"(af[mi][0]), "r"(af[mi][1]),
                          "r"(af[mi][2]), "r"(af[mi][3]),
                          "r"(bf[ni][0]), "r"(bf[ni][1]));
                }
        }
    }

    // ---- epilogue ----
    #pragma unroll
    for (int mi = 0; mi < MI; mi++) {
        #pragma unroll
        for (int ni = 0; ni < NI; ni++) {
            int row = bm + wm + mi*16 + g;
            int col = bn + wn + ni*8 + 2*c;
            float bx = 0.f, by = 0.f;
            if (EPI == 1 || EPI == 2 || EPI == 3) { bx = bias[col]; by = bias[col+1]; }
            #pragma unroll
            for (int half_ = 0; half_ < 2; half_++) {
                int r = row + half_*8;
                float vx = acc[mi][ni][half_*2+0];
                float vy = acc[mi][ni][half_*2+1];
                if (EPI == 1 || EPI == 2 || EPI == 3) { vx += bx; vy += by; }
                if (EPI == 2) {
                    *(__half2*)(auxh + (size_t)r * ldc + col)
                        = __floats2half2_rn(gelu_exact(vx), gelu_exact(vy));
                    continue;
                }
                if (EPI == 3) {
                    int l = r >> 3, b = r & 7;
                    int which = col >> 10;
                    int e = col & 1023;
                    int h = e >> 6, d = e & 63;
                    int bh = b * HH + h;
                    if (which == 0) { vx *= 0.125f; vy *= 0.125f; }
                    if (which < 2) {
                        __half2* P = (__half2*)(auxh + (size_t)which * QSZ
                                                + ((size_t)bh * LSEQ + l) * HD + d);
                        *P = __floats2half2_rn(vx, vy);
                    } else {
                        // V transposed: [bh, d, s=l]
                        __half* Pv = auxh + 2 * QSZ + ((size_t)bh * HD + d) * LSEQ + l;
                        Pv[0]    = __float2half_rn(vx);
                        Pv[LSEQ] = __float2half_rn(vy);
                    }
                    continue;
                }
                if (EPI == 4) {
                    float2 o = *(float2*)(C + (size_t)r * ldc + col);
                    int l = blockIdx.z;
                    int b = r >> 4, h = r & 15;   // r = bh
                    __half2* P = (__half2*)(auxh + ((size_t)(l * BB + b) * EE)
                                            + h * HD + col);
                    *P = __floats2half2_rn(vx + o.x, vy + o.y);
                    continue;
                }
                float2* Cp = (float2*)(C + (size_t)r * ldc + col);
                if (ACCUM) {
                    float2 o = *Cp;
                    vx += o.x; vy += o.y;
                }
                *Cp = make_float2(vx, vy);
            }
        }
    }
}

// ---------------- pt = half(pos + typ), [l,s,d] ----------------
__global__ void add2h_kernel(const float4* __restrict__ a, const float4* __restrict__ b,
                             __half* __restrict__ o, int n4)
{
    int i = blockIdx.x * blockDim.x + threadIdx.x;
    if (i < n4) {
        float4 x = a[i], y = b[i];
        __half2* p = (__half2*)(o + (size_t)i * 4);
        p[0] = __floats2half2_rn(x.x + y.x, x.y + y.y);
        p[1] = __floats2half2_rn(x.z + y.z, x.w + y.w);
    }
}

// ---------------- fp32 -> half ----------------
__global__ void f2h_kernel(const float4* __restrict__ a, __half* __restrict__ o, int n4)
{
    int i = blockIdx.x * blockDim.x + threadIdx.x;
    if (i < n4) {
        float4 x = a[i];
        __half2* p = (__half2*)(o + (size_t)i * 4);
        p[0] = __floats2half2_rn(x.x, x.y);
        p[1] = __floats2half2_rn(x.z, x.w);
    }
}

// ---------------- transpose PTh [l,s,d] -> PTt [l,d,s], one block per l ----------------
__global__ void ptT_kernel(const __half* __restrict__ PTh, __half* __restrict__ PTt)
{
    __shared__ __half tile[64][72];
    int l = blockIdx.x;
    int t = threadIdx.x;   // 256
    for (int st = 0; st < 8; st++) {
        for (int i = t; i < 64 * 8; i += 256) {        // 64 s-rows x 8 uint4 chunks
            int s = i >> 3, ch = i & 7;
            uint4 v = *(const uint4*)(PTh + ((size_t)l * LSEQ + st*64 + s) * HD + ch*8);
            *(uint4*)&tile[s][ch*8] = v;
        }
        __syncthreads();
        for (int i = t; i < 64 * 32; i += 256) {       // 64 d-rows x 32 half2
            int d = i >> 5;
            int s2 = (i & 31) * 2;
            __half2 h = __halves2half2(tile[s2][d], tile[s2+1][d]);
            *(__half2*)(PTt + ((size_t)l * HD + d) * LSEQ + st*64 + s2) = h;
        }
        __syncthreads();
    }
}

// ---------------- softmax over rows of 512 (warp per row), fp32 in -> half out ----------------
__global__ void softmax512_kernel(const float* __restrict__ S, __half* __restrict__ W)
{
    long long row = (long long)blockIdx.x * 8 + threadIdx.y;
    const float4* p4 = (const float4*)(S + row * LSEQ);
    int lane = threadIdx.x;
    float v[16];
    #pragma unroll
    for (int j = 0; j < 4; j++) {
        float4 t = p4[lane * 4 + j];
        v[j*4+0] = t.x; v[j*4+1] = t.y; v[j*4+2] = t.z; v[j*4+3] = t.w;
    }
    float mx = -1e30f;
    #pragma unroll
    for (int i = 0; i < 16; i++) mx = fmaxf(mx, v[i]);
    #pragma unroll
    for (int o = 16; o; o >>= 1) mx = fmaxf(mx, __shfl_xor_sync(0xffffffffu, mx, o));
    float s = 0.f;
    #pragma unroll
    for (int i = 0; i < 16; i++) { v[i] = __expf(v[i] - mx); s += v[i]; }
    #pragma unroll
    for (int o = 16; o; o >>= 1) s += __shfl_xor_sync(0xffffffffu, s, o);
    float inv = 1.0f / s;
    __half2* w2 = (__half2*)(W + row * LSEQ + lane * 16);
    #pragma unroll
    for (int i = 0; i < 8; i++)
        w2[i] = __floats2half2_rn(v[2*i] * inv, v[2*i+1] * inv);
}

// ---------------- LN(residual); exact fp32 out + optional half copy ----------------
__global__ void ln_res_kernel(const float* __restrict__ X, const float* __restrict__ Y,
                              const float* __restrict__ g, const float* __restrict__ be,
                              float* __restrict__ O, __half* __restrict__ Oh)
{
    int row = blockIdx.x;
    int t = threadIdx.x;      // 256 threads, 1 float4 each
    const float4* x4 = (const float4*)(X + (size_t)row * EE);
    const float4* y4 = (const float4*)(Y + (size_t)row * EE);
    float4 a = x4[t], b = y4[t];
    float4 v = make_float4(a.x+b.x, a.y+b.y, a.z+b.z, a.w+b.w);
    float s = v.x + v.y + v.z + v.w;
    float q = v.x*v.x + v.y*v.y + v.z*v.z + v.w*v.w;
    __shared__ float sh_s[8], sh_q[8];
    #pragma unroll
    for (int o = 16; o; o >>= 1) {
        s += __shfl_xor_sync(0xffffffffu, s, o);
        q += __shfl_xor_sync(0xffffffffu, q, o);
    }
    int wid = t >> 5, lane = t & 31;
    if (!lane) { sh_s[wid] = s; sh_q[wid] = q; }
    __syncthreads();
    if (t < 32) {
        s = (lane < 8) ? sh_s[lane] : 0.f;
        q = (lane < 8) ? sh_q[lane] : 0.f;
        #pragma unroll
        for (int o = 4; o; o >>= 1) {
            s += __shfl_xor_sync(0xffffffffu, s, o);
            q += __shfl_xor_sync(0xffffffffu, q, o);
        }
        if (!lane) { sh_s[0] = s; sh_q[0] = q; }
    }
    __syncthreads();
    float mean = sh_s[0] * (1.f/EE);
    float var  = sh_q[0] * (1.f/EE) - mean * mean;
    float r = rsqrtf(var + 1e-5f);
    float4 gg = ((const float4*)g)[t];
    float4 bb = ((const float4*)be)[t];
    float4 o;
    o.x = (v.x - mean) * r * gg.x + bb.x;
    o.y = (v.y - mean) * r * gg.y + bb.y;
    o.z = (v.z - mean) * r * gg.z + bb.z;
    o.w = (v.w - mean) * r * gg.w + bb.w;
    ((float4*)(O + (size_t)row * EE))[t] = o;
    if (Oh) {
        __half2* p = (__half2*)(Oh + (size_t)row * EE + t * 4);
        p[0] = __floats2half2_rn(o.x, o.y);
        p[1] = __floats2half2_rn(o.z, o.w);
    }
}

// ---------------- launch ----------------
static void* symv(const void* devSymbol) {
    void* p = nullptr;
    cudaGetSymbolAddress(&p, devSymbol);
    return p;
}

#define SMEM_128x128 (3 * (128*40 + 128*40) * 2)   // 61440
#define SMEM_128x64  (3 * (128*40 +  64*40) * 2)   // 46080

extern "C" void kernel_launch(void* const* d_in, const int* in_sizes, int n_in,
                              void* d_out, int out_size)
{
    const float* src = (const float*)d_in[0];
    const float* pos = (const float*)d_in[1];
    const float* typ = (const float*)d_in[2];
    const float* Wi  = (const float*)d_in[3];
    const float* bi  = (const float*)d_in[4];
    const float* Wo  = (const float*)d_in[5];
    const float* bo  = (const float*)d_in[6];
    const float* W1  = (const float*)d_in[7];
    const float* b1  = (const float*)d_in[8];
    const float* W2  = (const float*)d_in[9];
    const float* b2  = (const float*)d_in[10];
    const float* g1  = (const float*)d_in[11];
    const float* be1 = (const float*)d_in[12];
    const float* g2  = (const float*)d_in[13];
    const float* be2 = (const float*)d_in[14];
    float* out = (float*)d_out;

    __half* PTh  = (__half*)symv(g_PTh);
    __half* PTt  = (__half*)symv(g_PTt);
    __half* QKVh = (__half*)symv(g_QKVh);
    __half* Q = QKVh, *K = QKVh + QSZ, *Vt = QKVh + 2*QSZ;
    float*  S    = (float*)symv(g_S4);
    __half* Wh   = (__half*)symv(g_Wh);
    float*  AO   = (float*)symv(g_AO4);
    __half* AL   = (__half*)symv(g_ALh);
    float*  Y    = (float*)symv(g_Y4);
    float*  X1   = (float*)symv(g_X14);
    __half* X1h  = (__half*)symv(g_X1h);
    float*  X    = (float*)symv(g_X4);
    __half* Xh   = (__half*)symv(g_Xh);
    __half* Hh   = (__half*)symv(g_Hh);
    __half* Wih  = (__half*)symv(g_Wih);
    __half* Woh  = (__half*)symv(g_Woh);
    __half* W1h  = (__half*)symv(g_W1h);
    __half* W2h  = (__half*)symv(g_W2h);

    static bool attrs_done = false;
    if (!attrs_done) {
        cudaFuncSetAttribute(hgemm<128,128,64,32,3,false>,
                             cudaFuncAttributeMaxDynamicSharedMemorySize, SMEM_128x128);
        cudaFuncSetAttribute(hgemm<128,128,64,32,0,false>,
                             cudaFuncAttributeMaxDynamicSharedMemorySize, SMEM_128x128);
        cudaFuncSetAttribute(hgemm<128,128,64,32,0,true>,
                             cudaFuncAttributeMaxDynamicSharedMemorySize, SMEM_128x128);
        cudaFuncSetAttribute(hgemm<128,128,64,32,1,false>,
                             cudaFuncAttributeMaxDynamicSharedMemorySize, SMEM_128x128);
        cudaFuncSetAttribute(hgemm<128,128,64,32,2,false>,
                             cudaFuncAttributeMaxDynamicSharedMemorySize, SMEM_128x128);
        cudaFuncSetAttribute(hgemm<128,64,32,32,0,false>,
                             cudaFuncAttributeMaxDynamicSharedMemorySize, SMEM_128x64);
        cudaFuncSetAttribute(hgemm<128,64,32,32,4,false>,
                             cudaFuncAttributeMaxDynamicSharedMemorySize, SMEM_128x64);
        attrs_done = true;
    }

    // one-time conversions / pt build
    add2h_kernel<<<PT_ELEMS/4/256, 256>>>((const float4*)pos, (const float4*)typ,
                                          PTh, PT_ELEMS/4);
    ptT_kernel<<<LSEQ, 256>>>(PTh, PTt);
    f2h_kernel<<<(NLAY*3*EE*EE/4)/256, 256>>>((const float4*)Wi, Wih, NLAY*3*EE*EE/4);
    f2h_kernel<<<(NLAY*EE*EE/4)/256,   256>>>((const float4*)Wo, Woh, NLAY*EE*EE/4);
    f2h_kernel<<<(NLAY*DFF*EE/4)/256,  256>>>((const float4*)W1, W1h, NLAY*DFF*EE/4);
    f2h_kernel<<<(NLAY*EE*DFF/4)/256,  256>>>((const float4*)W2, W2h, NLAY*EE*DFF/4);
    f2h_kernel<<<(MROWS*EE/4)/256,     256>>>((const float4*)src, Xh, MROWS*EE/4);

    const float* x = src;     // exact residual input
    for (int l = 0; l < NLAY; l++) {
        // 1) QKV GEMM + fused split epilogue -> Q|K [bh,l,d], V [bh,d,s]
        hgemm<128,128,64,32,3,false><<<dim3(24,32,1), 256, SMEM_128x128>>>(
            Xh, EE, 0, Wih + (size_t)l*3*EE*EE, EE, 0,
            nullptr, 0, 0, bi + (size_t)l*3*EE, QKVh, MROWS, 3*EE, EE);

        // 2) S = Q @ K^T  (batched over bh)  [512,512] K=64
        hgemm<128,128,64,32,0,false><<<dim3(4,4,BHN), 256, SMEM_128x128>>>(
            Q, HD, (long long)LSEQ*HD, K, HD, (long long)LSEQ*HD,
            S, LSEQ, (long long)LSEQ*LSEQ, nullptr, nullptr, LSEQ, LSEQ, HD);

        // 3) S[:,l,:] += Q[:,l,:] @ PTh[l]^T (batched over l)  [128,512] K=64
        hgemm<128,128,64,32,0,true><<<dim3(4,1,LSEQ), 256, SMEM_128x128>>>(
            Q, LSEQ*HD, (long long)HD,
            PTh, HD, (long long)LSEQ*HD,
            S, LSEQ*LSEQ, (long long)LSEQ,
            nullptr, nullptr, BHN, LSEQ, HD);

        // 4) softmax rows -> half weights Wh
        softmax512_kernel<<<BHN*LSEQ/8, dim3(32,8)>>>(S, Wh);

        // 5) AO = Wh @ Vt^T (batched over bh)  [512,64] K=512  (NT: Vt is [d,s])
        hgemm<128,64,32,32,0,false><<<dim3(1,4,BHN), 256, SMEM_128x64>>>(
            Wh, LSEQ, (long long)LSEQ*LSEQ, Vt, LSEQ, (long long)HD*LSEQ,
            AO, HD, (long long)LSEQ*HD, nullptr, nullptr, LSEQ, HD, LSEQ);

        // 6) AL[l,b,e] = half(AO + Wh[:,l,:] @ PTt[l]^T) (batched over l), fused reorder
        hgemm<128,64,32,32,4,false><<<dim3(1,1,LSEQ), 256, SMEM_128x64>>>(
            Wh, LSEQ*LSEQ, (long long)LSEQ,
            PTt, LSEQ, (long long)HD*LSEQ,
            AO, LSEQ*HD, (long long)HD,
            nullptr, AL, BHN, HD, LSEQ);

        // 7) Y = AL @ Wo^T + bo   [4096,1024] K=1024
        hgemm<128,128,64,32,1,false><<<dim3(8,32,1), 256, SMEM_128x128>>>(
            AL, EE, 0, Woh + (size_t)l*EE*EE, EE, 0,
            Y, EE, 0, bo + (size_t)l*EE, nullptr, MROWS, EE, EE);

        // 8) X1 = LN(x + Y)  (exact) + X1h (half)
        ln_res_kernel<<<MROWS, 256>>>(x, Y, g1 + (size_t)l*EE, be1 + (size_t)l*EE, X1, X1h);

        // 9) Hh = half(gelu(X1h @ W1^T + b1))   [4096,4096] K=1024
        hgemm<128,128,64,32,2,false><<<dim3(32,32,1), 256, SMEM_128x128>>>(
            X1h, EE, 0, W1h + (size_t)l*DFF*EE, EE, 0,
            nullptr, DFF, 0, b1 + (size_t)l*DFF, Hh, MROWS, DFF, EE);

        // 10) Y = Hh @ W2^T + b2   [4096,1024] K=4096
        hgemm<128,128,64,32,1,false><<<dim3(8,32,1), 256, SMEM_128x128>>>(
            Hh, DFF, 0, W2h + (size_t)l*EE*DFF, DFF, 0,
            Y, EE, 0, b2 + (size_t)l*EE, nullptr, MROWS, EE, DFF);

        // 11) next = LN(X1 + Y); last layer -> d_out (exact), else X + half Xh
        float*  xo  = (l == NLAY-1) ? out : X;
        __half* xoh = (l == NLAY-1) ? nullptr : Xh;
        ln_res_kernel<<<MROWS, 256>>>(X1, Y, g2 + (size_t)l*EE, be2 + (size_t)l*EE, xo, xoh);

        x = X;
    }
}

// round 8
// speedup vs baseline: 1.4733x; 1.0909x over previous
#include <cuda_runtime.h>
#include <cuda_fp16.h>
#include <math.h>
#include <stdint.h>

// ---------------- problem constants ----------------
#define LSEQ 512
#define BB   8
#define EE   1024
#define HH   16
#define HD   64
#define NLAY 2
#define DFF  4096
#define MROWS (LSEQ*BB)          // 4096
#define BHN  (BB*HH)             // 128
#define QSZ  ((size_t)BHN*LSEQ*HD)
#define PT_ELEMS ((size_t)LSEQ*LSEQ*HD)

// ---------------- scratch (device globals, uint4 for 16B alignment) ----------------
__device__ uint4  g_PTh [PT_ELEMS/8];                 // pos+typ half [l,s,d]
__device__ uint4  g_PTt [PT_ELEMS/8];                 // pos+typ half [l,d,s]
__device__ uint4  g_QKVh[3*QSZ/8];                    // Q|K half [bh,l,d]; V half [bh,d,s]
__device__ float4 g_S4  [(size_t)BHN*LSEQ*LSEQ/4];    // scores fp32 [bh,l,s]
__device__ uint4  g_Wh  [(size_t)BHN*LSEQ*LSEQ/8];    // softmax weights half [bh,l,s]
__device__ float4 g_AO4 [(size_t)BHN*LSEQ*HD/4];      // attn out fp32 [bh,l,d]
__device__ uint4  g_ALh [(size_t)MROWS*EE/8];         // attn out half [l,b,e]
__device__ float4 g_Y4  [(size_t)MROWS*EE/4];
__device__ float4 g_X14 [(size_t)MROWS*EE/4];         // exact LN1 out
__device__ uint4  g_X1h [(size_t)MROWS*EE/8];         // half LN1 out
__device__ float4 g_X4  [(size_t)MROWS*EE/4];         // exact layer out
__device__ uint4  g_Xh  [(size_t)MROWS*EE/8];         // half layer in
__device__ uint4  g_Hh  [(size_t)MROWS*DFF/8];        // ffn hidden half
// half weights
__device__ uint4  g_Wih [(size_t)NLAY*3*EE*EE/8];
__device__ uint4  g_Woh [(size_t)NLAY*EE*EE/8];
__device__ uint4  g_W1h [(size_t)NLAY*DFF*EE/8];
__device__ uint4  g_W2h [(size_t)NLAY*EE*DFF/8];

__device__ __forceinline__ float gelu_exact(float x) {
    return 0.5f * x * (1.0f + erff(x * 0.70710678118654752f));
}

__device__ __forceinline__ void cp16(uint32_t saddr, const void* gaddr) {
    asm volatile("cp.async.cg.shared.global [%0], [%1], 16;\n"
                 :: "r"(saddr), "l"(gaddr));
}
__device__ __forceinline__ void cp_commit() {
    asm volatile("cp.async.commit_group;\n");
}
template<int N>
__device__ __forceinline__ void cp_wait() {
    asm volatile("cp.async.wait_group %0;\n" :: "n"(N));
}
__device__ __forceinline__ uint32_t smem_u32(const void* p) {
    uint32_t a;
    asm("{ .reg .u64 t; cvta.to.shared.u64 t, %1; cvt.u32.u64 %0, t; }"
        : "=r"(a) : "l"(p));
    return a;
}
__device__ __forceinline__ void ldsm_x4(uint32_t& r0, uint32_t& r1,
                                        uint32_t& r2, uint32_t& r3, uint32_t saddr)
{
    asm volatile("ldmatrix.sync.aligned.m8n8.x4.shared.b16 {%0,%1,%2,%3}, [%4];"
                 : "=r"(r0), "=r"(r1), "=r"(r2), "=r"(r3) : "r"(saddr));
}

// ---------------- FP16 tensor-core GEMM (NT), cp.async 3-stage + ldmatrix ----------------
// C[M,N] (+)= A[M,K] * B[N,K]^T, fp32 accumulate.
// EPI: 0 plain fp32 C (ACCUM optional); 1 +bias -> fp32 C;
//      2 +bias, gelu -> half auxh[r*ldc+col];
//      3 qkv split: +bias, (q*0.125), half -> Q|K [bh,l,d], V -> [bh,d,s] in auxh;
//      4 read fp32 C (AO), add, half -> auxh[(l*BB+b)*EE + h*HD + col], l=blockIdx.z.
template<int BM, int BN, int WM, int WN, int EPI, bool ACCUM>
__global__ void __launch_bounds__((BM/WM)*(BN/WN)*32, 2)
hgemm(const __half* __restrict__ A, int lda, long long sAz,
      const __half* __restrict__ B, int ldb, long long sBz,
      float* __restrict__ C, int ldc, long long sCz,
      const float* __restrict__ bias, __half* __restrict__ auxh,
      int M, int N, int K)
{
    constexpr int BK = 32;                  // halves in k per stage
    constexpr int WARPS_M = BM / WM;
    constexpr int WARPS_N = BN / WN;
    constexpr int THREADS = WARPS_M * WARPS_N * 32;
    constexpr int LDSA = BK + 8;            // 40 halves -> 80B rows; ldmatrix conflict-free
    constexpr int A_HALVES = BM * LDSA;
    constexpr int B_HALVES = BN * LDSA;
    constexpr int STAGE_HALVES = A_HALVES + B_HALVES;
    constexpr int NSTAGE = 3;
    constexpr int MI = WM / 16;
    constexpr int NI = WN / 8;              // even (pairs for ldmatrix.x4)

    extern __shared__ __half smem[];

    A += (long long)blockIdx.z * sAz;
    B += (long long)blockIdx.z * sBz;
    C += (long long)blockIdx.z * sCz;

    const int bm = blockIdx.y * BM;
    const int bn = blockIdx.x * BN;
    const int tid  = threadIdx.x;
    const int wid  = tid >> 5;
    const int lane = tid & 31;
    const int wm = (wid / WARPS_N) * WM;
    const int wn = (wid % WARPS_N) * WN;
    const int g = lane >> 2;
    const int c = lane & 3;

    uint32_t smem_base = smem_u32(smem);

    // ldmatrix per-lane address components
    const int a_row = (lane & 15);            // row within 16-row fragment
    const int a_kof = (lane >> 4) << 3;       // 0 | 8 k-offset (matrices 2,3)
    const int b_row = ((lane >> 4) << 3) + (lane & 7);  // row within 16-n pair
    const int b_kof = ((lane >> 3) & 1) << 3; // 0 | 8 k-offset

    float acc[MI][NI][4];
    #pragma unroll
    for (int mi = 0; mi < MI; mi++)
        #pragma unroll
        for (int ni = 0; ni < NI; ni++)
            #pragma unroll
            for (int r = 0; r < 4; r++) acc[mi][ni][r] = 0.f;

    const int nIter = K / BK;

    auto load_tiles = [&](int stage, int k0) {
        uint32_t sA = smem_base + (uint32_t)(stage * STAGE_HALVES) * 2u;
        uint32_t sB = sA + (uint32_t)A_HALVES * 2u;
        #pragma unroll
        for (int i = tid; i < BM * (BK/8); i += THREADS) {
            int row = i / (BK/8);
            int kc  = (i % (BK/8)) * 8;
            cp16(sA + (uint32_t)(row * LDSA + kc) * 2u,
                 A + (size_t)(bm + row) * lda + k0 + kc);
        }
        #pragma unroll
        for (int i = tid; i < BN * (BK/8); i += THREADS) {
            int row = i / (BK/8);
            int kc  = (i % (BK/8)) * 8;
            cp16(sB + (uint32_t)(row * LDSA + kc) * 2u,
                 B + (size_t)(bn + row) * ldb + k0 + kc);
        }
        cp_commit();
    };

    load_tiles(0, 0);
    if (nIter > 1) load_tiles(1, BK);

    for (int it = 0; it < nIter; it++) {
        if (it + 2 < nIter) { cp_wait<1>(); } else { cp_wait<0>(); }
        __syncthreads();
        if (it + 2 < nIter) load_tiles((it + 2) % NSTAGE, (it + 2) * BK);

        const uint32_t sAb = smem_base + (uint32_t)((it % NSTAGE) * STAGE_HALVES) * 2u;
        const uint32_t sBb = sAb + (uint32_t)A_HALVES * 2u;

        #pragma unroll
        for (int kk = 0; kk < BK; kk += 16) {
            uint32_t af[MI][4], bf[NI][2];
            #pragma unroll
            for (int mi = 0; mi < MI; mi++) {
                uint32_t addr = sAb + (uint32_t)((wm + mi*16 + a_row) * LDSA
                                                 + kk + a_kof) * 2u;
                ldsm_x4(af[mi][0], af[mi][1], af[mi][2], af[mi][3], addr);
            }
            #pragma unroll
            for (int p = 0; p < NI/2; p++) {
                uint32_t addr = sBb + (uint32_t)((wn + p*16 + b_row) * LDSA
                                                 + kk + b_kof) * 2u;
                ldsm_x4(bf[2*p][0], bf[2*p][1], bf[2*p+1][0], bf[2*p+1][1], addr);
            }
            #pragma unroll
            for (int mi = 0; mi < MI; mi++)
                #pragma unroll
                for (int ni = 0; ni < NI; ni++) {
                    asm volatile(
                        "mma.sync.aligned.m16n8k16.row.col.f32.f16.f16.f32 "
                        "{%0,%1,%2,%3}, {%4,%5,%6,%7}, {%8,%9}, {%0,%1,%2,%3};\n"
                        : "+f"(acc[mi][ni][0]), "+f"(acc[mi][ni][1]),
                          "+f"(acc[mi][ni][2]), "+f"(acc[mi][ni][3])
                        : "r"(af[mi][0]), "r"(af[mi][1]),
                          "r"(af[mi][2]), "r"(af[mi][3]),
                          "r"(bf[ni][0]), "r"(bf[ni][1]));
                }
        }
    }

    // ---- epilogue ----
    #pragma unroll
    for (int mi = 0; mi < MI; mi++) {
        #pragma unroll
        for (int ni = 0; ni < NI; ni++) {
            int row = bm + wm + mi*16 + g;
            int col = bn + wn + ni*8 + 2*c;
            float bx = 0.f, by = 0.f;
            if (EPI == 1 || EPI == 2 || EPI == 3) { bx = bias[col]; by = bias[col+1]; }
            #pragma unroll
            for (int half_ = 0; half_ < 2; half_++) {
                int r = row + half_*8;
                float vx = acc[mi][ni][half_*2+0];
                float vy = acc[mi][ni][half_*2+1];
                if (EPI == 1 || EPI == 2 || EPI == 3) { vx += bx; vy += by; }
                if (EPI == 2) {
                    *(__half2*)(auxh + (size_t)r * ldc + col)
                        = __floats2half2_rn(gelu_exact(vx), gelu_exact(vy));
                    continue;
                }
                if (EPI == 3) {
                    int l = r >> 3, b = r & 7;
                    int which = col >> 10;
                    int e = col & 1023;
                    int h = e >> 6, d = e & 63;
                    int bh = b * HH + h;
                    if (which == 0) { vx *= 0.125f; vy *= 0.125f; }
                    if (which < 2) {
                        __half2* P = (__half2*)(auxh + (size_t)which * QSZ
                                                + ((size_t)bh * LSEQ + l) * HD + d);
                        *P = __floats2half2_rn(vx, vy);
                    } else {
                        // V transposed: [bh, d, s=l]
                        __half* Pv = auxh + 2 * QSZ + ((size_t)bh * HD + d) * LSEQ + l;
                        Pv[0]    = __float2half_rn(vx);
                        Pv[LSEQ] = __float2half_rn(vy);
                    }
                    continue;
                }
                if (EPI == 4) {
                    float2 o = *(float2*)(C + (size_t)r * ldc + col);
                    int l = blockIdx.z;
                    int b = r >> 4, h = r & 15;   // r = bh
                    __half2* P = (__half2*)(auxh + ((size_t)(l * BB + b) * EE)
                                            + h * HD + col);
                    *P = __floats2half2_rn(vx + o.x, vy + o.y);
                    continue;
                }
                float2* Cp = (float2*)(C + (size_t)r * ldc + col);
                if (ACCUM) {
                    float2 o = *Cp;
                    vx += o.x; vy += o.y;
                }
                *Cp = make_float2(vx, vy);
            }
        }
    }
}

// ---------------- pt = half(pos + typ), [l,s,d] ----------------
__global__ void add2h_kernel(const float4* __restrict__ a, const float4* __restrict__ b,
                             __half* __restrict__ o, int n4)
{
    int i = blockIdx.x * blockDim.x + threadIdx.x;
    if (i < n4) {
        float4 x = a[i], y = b[i];
        __half2* p = (__half2*)(o + (size_t)i * 4);
        p[0] = __floats2half2_rn(x.x + y.x, x.y + y.y);
        p[1] = __floats2half2_rn(x.z + y.z, x.w + y.w);
    }
}

// ---------------- fp32 -> half ----------------
__global__ void f2h_kernel(const float4* __restrict__ a, __half* __restrict__ o, int n4)
{
    int i = blockIdx.x * blockDim.x + threadIdx.x;
    if (i < n4) {
        float4 x = a[i];
        __half2* p = (__half2*)(o + (size_t)i * 4);
        p[0] = __floats2half2_rn(x.x, x.y);
        p[1] = __floats2half2_rn(x.z, x.w);
    }
}

// ---------------- transpose PTh [l,s,d] -> PTt [l,d,s] ----------------
__global__ void ptT_kernel(const __half* __restrict__ PTh, __half* __restrict__ PTt)
{
    __shared__ __half tile[64][72];
    int l = blockIdx.x;
    int t = threadIdx.x;   // 256
    for (int st = 0; st < 8; st++) {
        for (int i = t; i < 64 * 8; i += 256) {
            int s = i >> 3, ch = i & 7;
            uint4 v = *(const uint4*)(PTh + ((size_t)l * LSEQ + st*64 + s) * HD + ch*8);
            *(uint4*)&tile[s][ch*8] = v;
        }
        __syncthreads();
        for (int i = t; i < 64 * 32; i += 256) {
            int d = i >> 5;
            int s2 = (i & 31) * 2;
            __half2 h = __halves2half2(tile[s2][d], tile[s2+1][d]);
            *(__half2*)(PTt + ((size_t)l * HD + d) * LSEQ + st*64 + s2) = h;
        }
        __syncthreads();
    }
}

// ---------------- softmax rows of 512, fp32 in -> half out ----------------
__global__ void softmax512_kernel(const float* __restrict__ S, __half* __restrict__ W)
{
    long long row = (long long)blockIdx.x * 8 + threadIdx.y;
    const float4* p4 = (const float4*)(S + row * LSEQ);
    int lane = threadIdx.x;
    float v[16];
    #pragma unroll
    for (int j = 0; j < 4; j++) {
        float4 t = p4[lane * 4 + j];
        v[j*4+0] = t.x; v[j*4+1] = t.y; v[j*4+2] = t.z; v[j*4+3] = t.w;
    }
    float mx = -1e30f;
    #pragma unroll
    for (int i = 0; i < 16; i++) mx = fmaxf(mx, v[i]);
    #pragma unroll
    for (int o = 16; o; o >>= 1) mx = fmaxf(mx, __shfl_xor_sync(0xffffffffu, mx, o));
    float s = 0.f;
    #pragma unroll
    for (int i = 0; i < 16; i++) { v[i] = __expf(v[i] - mx); s += v[i]; }
    #pragma unroll
    for (int o = 16; o; o >>= 1) s += __shfl_xor_sync(0xffffffffu, s, o);
    float inv = 1.0f / s;
    __half2* w2 = (__half2*)(W + row * LSEQ + lane * 16);
    #pragma unroll
    for (int i = 0; i < 8; i++)
        w2[i] = __floats2half2_rn(v[2*i] * inv, v[2*i+1] * inv);
}

// ---------------- LN(residual); exact fp32 out + optional half copy ----------------
__global__ void ln_res_kernel(const float* __restrict__ X, const float* __restrict__ Y,
                              const float* __restrict__ g, const float* __restrict__ be,
                              float* __restrict__ O, __half* __restrict__ Oh)
{
    int row = blockIdx.x;
    int t = threadIdx.x;
    const float4* x4 = (const float4*)(X + (size_t)row * EE);
    const float4* y4 = (const float4*)(Y + (size_t)row * EE);
    float4 a = x4[t], b = y4[t];
    float4 v = make_float4(a.x+b.x, a.y+b.y, a.z+b.z, a.w+b.w);
    float s = v.x + v.y + v.z + v.w;
    float q = v.x*v.x + v.y*v.y + v.z*v.z + v.w*v.w;
    __shared__ float sh_s[8], sh_q[8];
    #pragma unroll
    for (int o = 16; o; o >>= 1) {
        s += __shfl_xor_sync(0xffffffffu, s, o);
        q += __shfl_xor_sync(0xffffffffu, q, o);
    }
    int wid = t >> 5, lane = t & 31;
    if (!lane) { sh_s[wid] = s; sh_q[wid] = q; }
    __syncthreads();
    if (t < 32) {
        s = (lane < 8) ? sh_s[lane] : 0.f;
        q = (lane < 8) ? sh_q[lane] : 0.f;
        #pragma unroll
        for (int o = 4; o; o >>= 1) {
            s += __shfl_xor_sync(0xffffffffu, s, o);
            q += __shfl_xor_sync(0xffffffffu, q, o);
        }
        if (!lane) { sh_s[0] = s; sh_q[0] = q; }
    }
    __syncthreads();
    float mean = sh_s[0] * (1.f/EE);
    float var  = sh_q[0] * (1.f/EE) - mean * mean;
    float r = rsqrtf(var + 1e-5f);
    float4 gg = ((const float4*)g)[t];
    float4 bb = ((const float4*)be)[t];
    float4 o;
    o.x = (v.x - mean) * r * gg.x + bb.x;
    o.y = (v.y - mean) * r * gg.y + bb.y;
    o.z = (v.z - mean) * r * gg.z + bb.z;
    o.w = (v.w - mean) * r * gg.w + bb.w;
    ((float4*)(O + (size_t)row * EE))[t] = o;
    if (Oh) {
        __half2* p = (__half2*)(Oh + (size_t)row * EE + t * 4);
        p[0] = __floats2half2_rn(o.x, o.y);
        p[1] = __floats2half2_rn(o.z, o.w);
    }
}

// ---------------- launch ----------------
static void* symv(const void* devSymbol) {
    void* p = nullptr;
    cudaGetSymbolAddress(&p, devSymbol);
    return p;
}

#define SMEM_H128x128 (3 * (128*40 + 128*40) * 2)   // 61440
#define SMEM_H128x64  (3 * (128*40 +  64*40) * 2)   // 46080

extern "C" void kernel_launch(void* const* d_in, const int* in_sizes, int n_in,
                              void* d_out, int out_size)
{
    const float* src = (const float*)d_in[0];
    const float* pos = (const float*)d_in[1];
    const float* typ = (const float*)d_in[2];
    const float* Wi  = (const float*)d_in[3];
    const float* bi  = (const float*)d_in[4];
    const float* Wo  = (const float*)d_in[5];
    const float* bo  = (const float*)d_in[6];
    const float* W1  = (const float*)d_in[7];
    const float* b1  = (const float*)d_in[8];
    const float* W2  = (const float*)d_in[9];
    const float* b2  = (const float*)d_in[10];
    const float* g1  = (const float*)d_in[11];
    const float* be1 = (const float*)d_in[12];
    const float* g2  = (const float*)d_in[13];
    const float* be2 = (const float*)d_in[14];
    float* out = (float*)d_out;

    __half* PTh  = (__half*)symv(g_PTh);
    __half* PTt  = (__half*)symv(g_PTt);
    __half* QKVh = (__half*)symv(g_QKVh);
    __half* Q = QKVh, *K = QKVh + QSZ, *Vt = QKVh + 2*QSZ;
    float*  S    = (float*)symv(g_S4);
    __half* Wh   = (__half*)symv(g_Wh);
    float*  AO   = (float*)symv(g_AO4);
    __half* AL   = (__half*)symv(g_ALh);
    float*  Y    = (float*)symv(g_Y4);
    float*  X1   = (float*)symv(g_X14);
    __half* X1h  = (__half*)symv(g_X1h);
    float*  X    = (float*)symv(g_X4);
    __half* Xh   = (__half*)symv(g_Xh);
    __half* Hh   = (__half*)symv(g_Hh);
    __half* Wih  = (__half*)symv(g_Wih);
    __half* Woh  = (__half*)symv(g_Woh);
    __half* W1h  = (__half*)symv(g_W1h);
    __half* W2h  = (__half*)symv(g_W2h);

    static bool attrs_done = false;
    if (!attrs_done) {
        cudaFuncSetAttribute(hgemm<128,128,64,32,3,false>,
                             cudaFuncAttributeMaxDynamicSharedMemorySize, SMEM_H128x128);
        cudaFuncSetAttribute(hgemm<128,128,64,32,0,false>,
                             cudaFuncAttributeMaxDynamicSharedMemorySize, SMEM_H128x128);
        cudaFuncSetAttribute(hgemm<128,128,64,32,0,true>,
                             cudaFuncAttributeMaxDynamicSharedMemorySize, SMEM_H128x128);
        cudaFuncSetAttribute(hgemm<128,128,64,32,1,false>,
                             cudaFuncAttributeMaxDynamicSharedMemorySize, SMEM_H128x128);
        cudaFuncSetAttribute(hgemm<128,128,64,32,2,false>,
                             cudaFuncAttributeMaxDynamicSharedMemorySize, SMEM_H128x128);
        cudaFuncSetAttribute(hgemm<128,64,32,32,0,false>,
                             cudaFuncAttributeMaxDynamicSharedMemorySize, SMEM_H128x64);
        cudaFuncSetAttribute(hgemm<128,64,32,32,4,false>,
                             cudaFuncAttributeMaxDynamicSharedMemorySize, SMEM_H128x64);
        attrs_done = true;
    }

    // one-time conversions / pt build
    add2h_kernel<<<PT_ELEMS/4/256, 256>>>((const float4*)pos, (const float4*)typ,
                                          PTh, PT_ELEMS/4);
    ptT_kernel<<<LSEQ, 256>>>(PTh, PTt);
    f2h_kernel<<<(NLAY*3*EE*EE/4)/256, 256>>>((const float4*)Wi, Wih, NLAY*3*EE*EE/4);
    f2h_kernel<<<(NLAY*EE*EE/4)/256,   256>>>((const float4*)Wo, Woh, NLAY*EE*EE/4);
    f2h_kernel<<<(NLAY*DFF*EE/4)/256,  256>>>((const float4*)W1, W1h, NLAY*DFF*EE/4);
    f2h_kernel<<<(NLAY*EE*DFF/4)/256,  256>>>((const float4*)W2, W2h, NLAY*EE*DFF/4);
    f2h_kernel<<<(MROWS*EE/4)/256,     256>>>((const float4*)src, Xh, MROWS*EE/4);

    const float* x = src;     // exact residual input
    for (int l = 0; l < NLAY; l++) {
        // 1) QKV GEMM + fused split epilogue -> Q|K [bh,l,d], V [bh,d,s]
        hgemm<128,128,64,32,3,false><<<dim3(24,32,1), 256, SMEM_H128x128>>>(
            Xh, EE, 0, Wih + (size_t)l*3*EE*EE, EE, 0,
            nullptr, 0, 0, bi + (size_t)l*3*EE, QKVh, MROWS, 3*EE, EE);

        // 2) S = Q @ K^T  (batched over bh)
        hgemm<128,128,64,32,0,false><<<dim3(4,4,BHN), 256, SMEM_H128x128>>>(
            Q, HD, (long long)LSEQ*HD, K, HD, (long long)LSEQ*HD,
            S, LSEQ, (long long)LSEQ*LSEQ, nullptr, nullptr, LSEQ, LSEQ, HD);

        // 3) S[:,l,:] += Q[:,l,:] @ PTh[l]^T (batched over l)
        hgemm<128,128,64,32,0,true><<<dim3(4,1,LSEQ), 256, SMEM_H128x128>>>(
            Q, LSEQ*HD, (long long)HD,
            PTh, HD, (long long)LSEQ*HD,
            S, LSEQ*LSEQ, (long long)LSEQ,
            nullptr, nullptr, BHN, LSEQ, HD);

        // 4) softmax rows -> half weights Wh
        softmax512_kernel<<<BHN*LSEQ/8, dim3(32,8)>>>(S, Wh);

        // 5) AO = Wh @ Vt^T (batched over bh)
        hgemm<128,64,32,32,0,false><<<dim3(1,4,BHN), 256, SMEM_H128x64>>>(
            Wh, LSEQ, (long long)LSEQ*LSEQ, Vt, LSEQ, (long long)HD*LSEQ,
            AO, HD, (long long)LSEQ*HD, nullptr, nullptr, LSEQ, HD, LSEQ);

        // 6) AL[l,b,e] = half(AO + Wh[:,l,:] @ PTt[l]^T), fused reorder
        hgemm<128,64,32,32,4,false><<<dim3(1,1,LSEQ), 256, SMEM_H128x64>>>(
            Wh, LSEQ*LSEQ, (long long)LSEQ,
            PTt, LSEQ, (long long)HD*LSEQ,
            AO, LSEQ*HD, (long long)HD,
            nullptr, AL, BHN, HD, LSEQ);

        // 7) Y = AL @ Wo^T + bo
        hgemm<128,128,64,32,1,false><<<dim3(8,32,1), 256, SMEM_H128x128>>>(
            AL, EE, 0, Woh + (size_t)l*EE*EE, EE, 0,
            Y, EE, 0, bo + (size_t)l*EE, nullptr, MROWS, EE, EE);

        // 8) X1 = LN(x + Y)  (exact) + X1h (half)
        ln_res_kernel<<<MROWS, 256>>>(x, Y, g1 + (size_t)l*EE, be1 + (size_t)l*EE, X1, X1h);

        // 9) Hh = half(gelu(X1h @ W1^T + b1))
        hgemm<128,128,64,32,2,false><<<dim3(32,32,1), 256, SMEM_H128x128>>>(
            X1h, EE, 0, W1h + (size_t)l*DFF*EE, EE, 0,
            nullptr, DFF, 0, b1 + (size_t)l*DFF, Hh, MROWS, DFF, EE);

        // 10) Y = Hh @ W2^T + b2
        hgemm<128,128,64,32,1,false><<<dim3(8,32,1), 256, SMEM_H128x128>>>(
            Hh, DFF, 0, W2h + (size_t)l*EE*DFF, DFF, 0,
            Y, EE, 0, b2 + (size_t)l*EE, nullptr, MROWS, EE, DFF);

        // 11) next = LN(X1 + Y); last layer -> d_out (exact), else X + half Xh
        float*  xo  = (l == NLAY-1) ? out : X;
        __half* xoh = (l == NLAY-1) ? nullptr : Xh;
        ln_res_kernel<<<MROWS, 256>>>(X1, Y, g2 + (size_t)l*EE, be2 + (size_t)l*EE, xo, xoh);

        x = X;
    }
}

// round 9
// speedup vs baseline: 1.6173x; 1.0977x over previous
#include <cuda_runtime.h>
#include <cuda_fp16.h>
#include <math.h>
#include <stdint.h>

// ---------------- problem constants ----------------
#define LSEQ 512
#define BB   8
#define EE   1024
#define HH   16
#define HD   64
#define NLAY 2
#define DFF  4096
#define MROWS (LSEQ*BB)          // 4096
#define BHN  (BB*HH)             // 128
#define QSZ  ((size_t)BHN*LSEQ*HD)
#define PT_ELEMS ((size_t)LSEQ*LSEQ*HD)

// ---------------- scratch (device globals, uint4 for 16B alignment) ----------------
__device__ uint4  g_PTh [PT_ELEMS/8];                 // pos+typ half [l,s,d]
__device__ uint4  g_PTt [PT_ELEMS/8];                 // pos+typ half [l,d,s]
__device__ uint4  g_QKVh[3*QSZ/8];                    // Q|K half [bh,l,d]; V half [bh,d,s]
__device__ float4 g_S4  [(size_t)BHN*LSEQ*LSEQ/4];    // scores fp32 [bh,l,s]
__device__ uint4  g_Wh  [(size_t)BHN*LSEQ*LSEQ/8];    // softmax weights half [bh,l,s]
__device__ float4 g_AO4 [(size_t)BHN*LSEQ*HD/4];      // attn out fp32 [bh,l,d]
__device__ uint4  g_ALh [(size_t)MROWS*EE/8];         // attn out half [l,b,e]
__device__ float4 g_Y4  [(size_t)MROWS*EE/4];
__device__ float4 g_X14 [(size_t)MROWS*EE/4];         // exact LN1 out
__device__ uint4  g_X1h [(size_t)MROWS*EE/8];         // half LN1 out
__device__ float4 g_X4  [(size_t)MROWS*EE/4];         // exact layer out
__device__ uint4  g_Xh  [(size_t)MROWS*EE/8];         // half layer in
__device__ uint4  g_Hh  [(size_t)MROWS*DFF/8];        // ffn hidden half
// half weights
__device__ uint4  g_Wih [(size_t)NLAY*3*EE*EE/8];
__device__ uint4  g_Woh [(size_t)NLAY*EE*EE/8];
__device__ uint4  g_W1h [(size_t)NLAY*DFF*EE/8];
__device__ uint4  g_W2h [(size_t)NLAY*EE*DFF/8];

__device__ __forceinline__ float gelu_exact(float x) {
    return 0.5f * x * (1.0f + erff(x * 0.70710678118654752f));
}

__device__ __forceinline__ void cp16(uint32_t saddr, const void* gaddr) {
    asm volatile("cp.async.cg.shared.global [%0], [%1], 16;\n"
                 :: "r"(saddr), "l"(gaddr));
}
__device__ __forceinline__ void cp_commit() {
    asm volatile("cp.async.commit_group;\n");
}
template<int N>
__device__ __forceinline__ void cp_wait() {
    asm volatile("cp.async.wait_group %0;\n" :: "n"(N));
}
__device__ __forceinline__ uint32_t smem_u32(const void* p) {
    uint32_t a;
    asm("{ .reg .u64 t; cvta.to.shared.u64 t, %1; cvt.u32.u64 %0, t; }"
        : "=r"(a) : "l"(p));
    return a;
}
__device__ __forceinline__ void ldsm_x4(uint32_t& r0, uint32_t& r1,
                                        uint32_t& r2, uint32_t& r3, uint32_t saddr)
{
    asm volatile("ldmatrix.sync.aligned.m8n8.x4.shared.b16 {%0,%1,%2,%3}, [%4];"
                 : "=r"(r0), "=r"(r1), "=r"(r2), "=r"(r3) : "r"(saddr));
}
__device__ __forceinline__ void mma_16816(float* acc, const uint32_t* a, const uint32_t* b)
{
    asm volatile(
        "mma.sync.aligned.m16n8k16.row.col.f32.f16.f16.f32 "
        "{%0,%1,%2,%3}, {%4,%5,%6,%7}, {%8,%9}, {%0,%1,%2,%3};\n"
        : "+f"(acc[0]), "+f"(acc[1]), "+f"(acc[2]), "+f"(acc[3])
        : "r"(a[0]), "r"(a[1]), "r"(a[2]), "r"(a[3]), "r"(b[0]), "r"(b[1]));
}

// ---------------- FP16 tensor-core GEMM (NT), cp.async 3-stage + ldmatrix ----------------
// C[M,N] (+)= A[M,K] * B[N,K]^T, fp32 accumulate.
// EPI: 0 plain fp32 C (ACCUM optional); 1 +bias -> fp32 C;
//      2 +bias, gelu -> half auxh[r*ldc+col];
//      3 qkv split: +bias, (q*0.125), half -> Q|K [bh,l,d], V -> [bh,d,s] in auxh;
//      4 read fp32 C (AO), add, half -> auxh[(l*BB+b)*EE + h*HD + col], l=blockIdx.z.
template<int BM, int BN, int WM, int WN, int EPI, bool ACCUM>
__global__ void __launch_bounds__((BM/WM)*(BN/WN)*32, 2)
hgemm(const __half* __restrict__ A, int lda, long long sAz,
      const __half* __restrict__ B, int ldb, long long sBz,
      float* __restrict__ C, int ldc, long long sCz,
      const float* __restrict__ bias, __half* __restrict__ auxh,
      int M, int N, int K)
{
    constexpr int BK = 32;
    constexpr int WARPS_M = BM / WM;
    constexpr int WARPS_N = BN / WN;
    constexpr int THREADS = WARPS_M * WARPS_N * 32;
    constexpr int LDSA = BK + 8;            // 40 halves; ldmatrix conflict-free
    constexpr int A_HALVES = BM * LDSA;
    constexpr int B_HALVES = BN * LDSA;
    constexpr int STAGE_HALVES = A_HALVES + B_HALVES;
    constexpr int NSTAGE = 3;
    constexpr int MI = WM / 16;
    constexpr int NI = WN / 8;

    extern __shared__ __half smem[];

    A += (long long)blockIdx.z * sAz;
    B += (long long)blockIdx.z * sBz;
    C += (long long)blockIdx.z * sCz;

    const int bm = blockIdx.y * BM;
    const int bn = blockIdx.x * BN;
    const int tid  = threadIdx.x;
    const int wid  = tid >> 5;
    const int lane = tid & 31;
    const int wm = (wid / WARPS_N) * WM;
    const int wn = (wid % WARPS_N) * WN;
    const int g = lane >> 2;
    const int c = lane & 3;

    uint32_t smem_base = smem_u32(smem);

    const int a_row = (lane & 15);
    const int a_kof = (lane >> 4) << 3;
    const int b_row = ((lane >> 4) << 3) + (lane & 7);
    const int b_kof = ((lane >> 3) & 1) << 3;

    float acc[MI][NI][4];
    #pragma unroll
    for (int mi = 0; mi < MI; mi++)
        #pragma unroll
        for (int ni = 0; ni < NI; ni++)
            #pragma unroll
            for (int r = 0; r < 4; r++) acc[mi][ni][r] = 0.f;

    const int nIter = K / BK;

    auto load_tiles = [&](int stage, int k0) {
        uint32_t sA = smem_base + (uint32_t)(stage * STAGE_HALVES) * 2u;
        uint32_t sB = sA + (uint32_t)A_HALVES * 2u;
        #pragma unroll
        for (int i = tid; i < BM * (BK/8); i += THREADS) {
            int row = i / (BK/8);
            int kc  = (i % (BK/8)) * 8;
            cp16(sA + (uint32_t)(row * LDSA + kc) * 2u,
                 A + (size_t)(bm + row) * lda + k0 + kc);
        }
        #pragma unroll
        for (int i = tid; i < BN * (BK/8); i += THREADS) {
            int row = i / (BK/8);
            int kc  = (i % (BK/8)) * 8;
            cp16(sB + (uint32_t)(row * LDSA + kc) * 2u,
                 B + (size_t)(bn + row) * ldb + k0 + kc);
        }
        cp_commit();
    };

    load_tiles(0, 0);
    if (nIter > 1) load_tiles(1, BK);

    for (int it = 0; it < nIter; it++) {
        if (it + 2 < nIter) { cp_wait<1>(); } else { cp_wait<0>(); }
        __syncthreads();
        if (it + 2 < nIter) load_tiles((it + 2) % NSTAGE, (it + 2) * BK);

        const uint32_t sAb = smem_base + (uint32_t)((it % NSTAGE) * STAGE_HALVES) * 2u;
        const uint32_t sBb = sAb + (uint32_t)A_HALVES * 2u;

        #pragma unroll
        for (int kk = 0; kk < BK; kk += 16) {
            uint32_t af[MI][4], bf[NI][2];
            #pragma unroll
            for (int mi = 0; mi < MI; mi++) {
                uint32_t addr = sAb + (uint32_t)((wm + mi*16 + a_row) * LDSA
                                                 + kk + a_kof) * 2u;
                ldsm_x4(af[mi][0], af[mi][1], af[mi][2], af[mi][3], addr);
            }
            #pragma unroll
            for (int p = 0; p < NI/2; p++) {
                uint32_t addr = sBb + (uint32_t)((wn + p*16 + b_row) * LDSA
                                                 + kk + b_kof) * 2u;
                ldsm_x4(bf[2*p][0], bf[2*p][1], bf[2*p+1][0], bf[2*p+1][1], addr);
            }
            #pragma unroll
            for (int mi = 0; mi < MI; mi++)
                #pragma unroll
                for (int ni = 0; ni < NI; ni++)
                    mma_16816(acc[mi][ni], af[mi], bf[ni]);
        }
    }

    // ---- epilogue ----
    #pragma unroll
    for (int mi = 0; mi < MI; mi++) {
        #pragma unroll
        for (int ni = 0; ni < NI; ni++) {
            int row = bm + wm + mi*16 + g;
            int col = bn + wn + ni*8 + 2*c;
            float bx = 0.f, by = 0.f;
            if (EPI == 1 || EPI == 2 || EPI == 3) { bx = bias[col]; by = bias[col+1]; }
            #pragma unroll
            for (int half_ = 0; half_ < 2; half_++) {
                int r = row + half_*8;
                float vx = acc[mi][ni][half_*2+0];
                float vy = acc[mi][ni][half_*2+1];
                if (EPI == 1 || EPI == 2 || EPI == 3) { vx += bx; vy += by; }
                if (EPI == 2) {
                    *(__half2*)(auxh + (size_t)r * ldc + col)
                        = __floats2half2_rn(gelu_exact(vx), gelu_exact(vy));
                    continue;
                }
                if (EPI == 3) {
                    int l = r >> 3, b = r & 7;
                    int which = col >> 10;
                    int e = col & 1023;
                    int h = e >> 6, d = e & 63;
                    int bh = b * HH + h;
                    if (which == 0) { vx *= 0.125f; vy *= 0.125f; }
                    if (which < 2) {
                        __half2* P = (__half2*)(auxh + (size_t)which * QSZ
                                                + ((size_t)bh * LSEQ + l) * HD + d);
                        *P = __floats2half2_rn(vx, vy);
                    } else {
                        __half* Pv = auxh + 2 * QSZ + ((size_t)bh * HD + d) * LSEQ + l;
                        Pv[0]    = __float2half_rn(vx);
                        Pv[LSEQ] = __float2half_rn(vy);
                    }
                    continue;
                }
                if (EPI == 4) {
                    float2 o = *(float2*)(C + (size_t)r * ldc + col);
                    int l = blockIdx.z;
                    int b = r >> 4, h = r & 15;   // r = bh
                    __half2* P = (__half2*)(auxh + ((size_t)(l * BB + b) * EE)
                                            + h * HD + col);
                    *P = __floats2half2_rn(vx + o.x, vy + o.y);
                    continue;
                }
                float2* Cp = (float2*)(C + (size_t)r * ldc + col);
                if (ACCUM) {
                    float2 o = *Cp;
                    vx += o.x; vy += o.y;
                }
                *Cp = make_float2(vx, vy);
            }
        }
    }
}

// ============ fused pt-score accumulate + softmax ============
// One block = (64 bh rows) x (all 512 s cols) for a fixed l.
// acc = Q[bh,l,:] @ PT[l]^T;  then += S (QK^T, fp32); softmax rows; write Wh half.
// grid (2, LSEQ), block 512 (16 warps, WM=32, WN=64).
__global__ void __launch_bounds__(512, 1)
score_pt_softmax(const __half* __restrict__ Qm, const __half* __restrict__ PT,
                 const float* __restrict__ S, __half* __restrict__ W)
{
    constexpr int BM = 64, BN = 512, BK = 32, LDSA = 40;
    constexpr int A_HALVES = BM * LDSA;       // 2560
    constexpr int B_HALVES = BN * LDSA;       // 20480
    constexpr int STAGE = A_HALVES + B_HALVES;
    constexpr int MI = 2, NI = 8, WARPS_N = 8;

    extern __shared__ __half smem[];
    __shared__ float redmx[BM][WARPS_N];
    __shared__ float redsm[BM][WARPS_N];

    const int l  = blockIdx.y;
    const int bm = blockIdx.x * BM;
    const int tid  = threadIdx.x;
    const int wid  = tid >> 5;
    const int lane = tid & 31;
    const int wm = (wid / WARPS_N) * 32;
    const int wn = (wid % WARPS_N) * 64;
    const int wnx = wid % WARPS_N;
    const int g = lane >> 2, c = lane & 3;

    uint32_t smem_base = smem_u32(smem);
    const int a_row = (lane & 15);
    const int a_kof = (lane >> 4) << 3;
    const int b_row = ((lane >> 4) << 3) + (lane & 7);
    const int b_kof = ((lane >> 3) & 1) << 3;

    auto load_tiles = [&](int stage, int k0) {
        uint32_t sA = smem_base + (uint32_t)(stage * STAGE) * 2u;
        uint32_t sB = sA + (uint32_t)A_HALVES * 2u;
        #pragma unroll
        for (int i = tid; i < BM * (BK/8); i += 512) {
            int row = i >> 2; int kc = (i & 3) * 8;
            cp16(sA + (uint32_t)(row * LDSA + kc) * 2u,
                 Qm + ((size_t)(bm + row) * LSEQ + l) * HD + k0 + kc);
        }
        #pragma unroll
        for (int i = tid; i < BN * (BK/8); i += 512) {
            int row = i >> 2; int kc = (i & 3) * 8;
            cp16(sB + (uint32_t)(row * LDSA + kc) * 2u,
                 PT + ((size_t)l * LSEQ + row) * HD + k0 + kc);
        }
        cp_commit();
    };

    float acc[MI][NI][4];
    #pragma unroll
    for (int mi = 0; mi < MI; mi++)
        #pragma unroll
        for (int ni = 0; ni < NI; ni++)
            #pragma unroll
            for (int r = 0; r < 4; r++) acc[mi][ni][r] = 0.f;

    load_tiles(0, 0);
    load_tiles(1, BK);

    #pragma unroll
    for (int it = 0; it < 2; it++) {
        if (it == 0) { cp_wait<1>(); } else { cp_wait<0>(); }
        __syncthreads();
        const uint32_t sAb = smem_base + (uint32_t)(it * STAGE) * 2u;
        const uint32_t sBb = sAb + (uint32_t)A_HALVES * 2u;
        #pragma unroll
        for (int kk = 0; kk < BK; kk += 16) {
            uint32_t af[MI][4], bf[NI][2];
            #pragma unroll
            for (int mi = 0; mi < MI; mi++) {
                uint32_t addr = sAb + (uint32_t)((wm + mi*16 + a_row) * LDSA
                                                 + kk + a_kof) * 2u;
                ldsm_x4(af[mi][0], af[mi][1], af[mi][2], af[mi][3], addr);
            }
            #pragma unroll
            for (int p = 0; p < NI/2; p++) {
                uint32_t addr = sBb + (uint32_t)((wn + p*16 + b_row) * LDSA
                                                 + kk + b_kof) * 2u;
                ldsm_x4(bf[2*p][0], bf[2*p][1], bf[2*p+1][0], bf[2*p+1][1], addr);
            }
            #pragma unroll
            for (int mi = 0; mi < MI; mi++)
                #pragma unroll
                for (int ni = 0; ni < NI; ni++)
                    mma_16816(acc[mi][ni], af[mi], bf[ni]);
        }
    }

    // ---- add S (QK^T) ----
    #pragma unroll
    for (int mi = 0; mi < MI; mi++)
        #pragma unroll
        for (int half_ = 0; half_ < 2; half_++) {
            int rl = wm + mi*16 + g + half_*8;
            const float* Sp = S + ((size_t)(bm + rl) * LSEQ + l) * LSEQ;
            #pragma unroll
            for (int ni = 0; ni < NI; ni++) {
                float2 o = *(const float2*)(Sp + wn + ni*8 + 2*c);
                acc[mi][ni][half_*2+0] += o.x;
                acc[mi][ni][half_*2+1] += o.y;
            }
        }

    // ---- row max ----
    #pragma unroll
    for (int mi = 0; mi < MI; mi++)
        #pragma unroll
        for (int half_ = 0; half_ < 2; half_++) {
            float m = -1e30f;
            #pragma unroll
            for (int ni = 0; ni < NI; ni++) {
                m = fmaxf(m, acc[mi][ni][half_*2+0]);
                m = fmaxf(m, acc[mi][ni][half_*2+1]);
            }
            m = fmaxf(m, __shfl_xor_sync(0xffffffffu, m, 1));
            m = fmaxf(m, __shfl_xor_sync(0xffffffffu, m, 2));
            if (c == 0) redmx[wm + mi*16 + g + half_*8][wnx] = m;
        }
    __syncthreads();

    // ---- exp + row sum ----
    #pragma unroll
    for (int mi = 0; mi < MI; mi++)
        #pragma unroll
        for (int half_ = 0; half_ < 2; half_++) {
            int rl = wm + mi*16 + g + half_*8;
            float m = redmx[rl][0];
            #pragma unroll
            for (int w = 1; w < WARPS_N; w++) m = fmaxf(m, redmx[rl][w]);
            float s = 0.f;
            #pragma unroll
            for (int ni = 0; ni < NI; ni++) {
                float vx = __expf(acc[mi][ni][half_*2+0] - m);
                float vy = __expf(acc[mi][ni][half_*2+1] - m);
                acc[mi][ni][half_*2+0] = vx;
                acc[mi][ni][half_*2+1] = vy;
                s += vx + vy;
            }
            s += __shfl_xor_sync(0xffffffffu, s, 1);
            s += __shfl_xor_sync(0xffffffffu, s, 2);
            if (c == 0) redsm[rl][wnx] = s;
        }
    __syncthreads();

    // ---- scale + write half ----
    #pragma unroll
    for (int mi = 0; mi < MI; mi++)
        #pragma unroll
        for (int half_ = 0; half_ < 2; half_++) {
            int rl = wm + mi*16 + g + half_*8;
            float s = 0.f;
            #pragma unroll
            for (int w = 0; w < WARPS_N; w++) s += redsm[rl][w];
            float inv = 1.0f / s;
            __half* Wp = W + ((size_t)(bm + rl) * LSEQ + l) * LSEQ;
            #pragma unroll
            for (int ni = 0; ni < NI; ni++) {
                *(__half2*)(Wp + wn + ni*8 + 2*c) =
                    __floats2half2_rn(acc[mi][ni][half_*2+0] * inv,
                                      acc[mi][ni][half_*2+1] * inv);
            }
        }
}

// ---------------- pt = half(pos + typ), [l,s,d] ----------------
__global__ void add2h_kernel(const float4* __restrict__ a, const float4* __restrict__ b,
                             __half* __restrict__ o, int n4)
{
    int i = blockIdx.x * blockDim.x + threadIdx.x;
    if (i < n4) {
        float4 x = a[i], y = b[i];
        __half2* p = (__half2*)(o + (size_t)i * 4);
        p[0] = __floats2half2_rn(x.x + y.x, x.y + y.y);
        p[1] = __floats2half2_rn(x.z + y.z, x.w + y.w);
    }
}

// ---------------- fp32 -> half ----------------
__global__ void f2h_kernel(const float4* __restrict__ a, __half* __restrict__ o, int n4)
{
    int i = blockIdx.x * blockDim.x + threadIdx.x;
    if (i < n4) {
        float4 x = a[i];
        __half2* p = (__half2*)(o + (size_t)i * 4);
        p[0] = __floats2half2_rn(x.x, x.y);
        p[1] = __floats2half2_rn(x.z, x.w);
    }
}

// ---------------- transpose PTh [l,s,d] -> PTt [l,d,s] ----------------
__global__ void ptT_kernel(const __half* __restrict__ PTh, __half* __restrict__ PTt)
{
    __shared__ __half tile[64][72];
    int l = blockIdx.x;
    int t = threadIdx.x;   // 256
    for (int st = 0; st < 8; st++) {
        for (int i = t; i < 64 * 8; i += 256) {
            int s = i >> 3, ch = i & 7;
            uint4 v = *(const uint4*)(PTh + ((size_t)l * LSEQ + st*64 + s) * HD + ch*8);
            *(uint4*)&tile[s][ch*8] = v;
        }
        __syncthreads();
        for (int i = t; i < 64 * 32; i += 256) {
            int d = i >> 5;
            int s2 = (i & 31) * 2;
            __half2 h = __halves2half2(tile[s2][d], tile[s2+1][d]);
            *(__half2*)(PTt + ((size_t)l * HD + d) * LSEQ + st*64 + s2) = h;
        }
        __syncthreads();
    }
}

// ---------------- LN(residual); exact fp32 out + optional half copy ----------------
__global__ void ln_res_kernel(const float* __restrict__ X, const float* __restrict__ Y,
                              const float* __restrict__ g, const float* __restrict__ be,
                              float* __restrict__ O, __half* __restrict__ Oh)
{
    int row = blockIdx.x;
    int t = threadIdx.x;
    const float4* x4 = (const float4*)(X + (size_t)row * EE);
    const float4* y4 = (const float4*)(Y + (size_t)row * EE);
    float4 a = x4[t], b = y4[t];
    float4 v = make_float4(a.x+b.x, a.y+b.y, a.z+b.z, a.w+b.w);
    float s = v.x + v.y + v.z + v.w;
    float q = v.x*v.x + v.y*v.y + v.z*v.z + v.w*v.w;
    __shared__ float sh_s[8], sh_q[8];
    #pragma unroll
    for (int o = 16; o; o >>= 1) {
        s += __shfl_xor_sync(0xffffffffu, s, o);
        q += __shfl_xor_sync(0xffffffffu, q, o);
    }
    int wid = t >> 5, lane = t & 31;
    if (!lane) { sh_s[wid] = s; sh_q[wid] = q; }
    __syncthreads();
    if (t < 32) {
        s = (lane < 8) ? sh_s[lane] : 0.f;
        q = (lane < 8) ? sh_q[lane] : 0.f;
        #pragma unroll
        for (int o = 4; o; o >>= 1) {
            s += __shfl_xor_sync(0xffffffffu, s, o);
            q += __shfl_xor_sync(0xffffffffu, q, o);
        }
        if (!lane) { sh_s[0] = s; sh_q[0] = q; }
    }
    __syncthreads();
    float mean = sh_s[0] * (1.f/EE);
    float var  = sh_q[0] * (1.f/EE) - mean * mean;
    float r = rsqrtf(var + 1e-5f);
    float4 gg = ((const float4*)g)[t];
    float4 bb = ((const float4*)be)[t];
    float4 o;
    o.x = (v.x - mean) * r * gg.x + bb.x;
    o.y = (v.y - mean) * r * gg.y + bb.y;
    o.z = (v.z - mean) * r * gg.z + bb.z;
    o.w = (v.w - mean) * r * gg.w + bb.w;
    ((float4*)(O + (size_t)row * EE))[t] = o;
    if (Oh) {
        __half2* p = (__half2*)(Oh + (size_t)row * EE + t * 4);
        p[0] = __floats2half2_rn(o.x, o.y);
        p[1] = __floats2half2_rn(o.z, o.w);
    }
}

// ---------------- launch ----------------
static void* symv(const void* devSymbol) {
    void* p = nullptr;
    cudaGetSymbolAddress(&p, devSymbol);
    return p;
}

#define SMEM_H128x128 (3 * (128*40 + 128*40) * 2)   // 61440
#define SMEM_H128x64  (3 * (128*40 +  64*40) * 2)   // 46080
#define SMEM_SS       (2 * (64*40 + 512*40) * 2)    // 92160

extern "C" void kernel_launch(void* const* d_in, const int* in_sizes, int n_in,
                              void* d_out, int out_size)
{
    const float* src = (const float*)d_in[0];
    const float* pos = (const float*)d_in[1];
    const float* typ = (const float*)d_in[2];
    const float* Wi  = (const float*)d_in[3];
    const float* bi  = (const float*)d_in[4];
    const float* Wo  = (const float*)d_in[5];
    const float* bo  = (const float*)d_in[6];
    const float* W1  = (const float*)d_in[7];
    const float* b1  = (const float*)d_in[8];
    const float* W2  = (const float*)d_in[9];
    const float* b2  = (const float*)d_in[10];
    const float* g1  = (const float*)d_in[11];
    const float* be1 = (const float*)d_in[12];
    const float* g2  = (const float*)d_in[13];
    const float* be2 = (const float*)d_in[14];
    float* out = (float*)d_out;

    __half* PTh  = (__half*)symv(g_PTh);
    __half* PTt  = (__half*)symv(g_PTt);
    __half* QKVh = (__half*)symv(g_QKVh);
    __half* Q = QKVh, *K = QKVh + QSZ, *Vt = QKVh + 2*QSZ;
    float*  S    = (float*)symv(g_S4);
    __half* Wh   = (__half*)symv(g_Wh);
    float*  AO   = (float*)symv(g_AO4);
    __half* AL   = (__half*)symv(g_ALh);
    float*  Y    = (float*)symv(g_Y4);
    float*  X1   = (float*)symv(g_X14);
    __half* X1h  = (__half*)symv(g_X1h);
    float*  X    = (float*)symv(g_X4);
    __half* Xh   = (__half*)symv(g_Xh);
    __half* Hh   = (__half*)symv(g_Hh);
    __half* Wih  = (__half*)symv(g_Wih);
    __half* Woh  = (__half*)symv(g_Woh);
    __half* W1h  = (__half*)symv(g_W1h);
    __half* W2h  = (__half*)symv(g_W2h);

    static bool attrs_done = false;
    if (!attrs_done) {
        cudaFuncSetAttribute(hgemm<128,128,64,32,3,false>,
                             cudaFuncAttributeMaxDynamicSharedMemorySize, SMEM_H128x128);
        cudaFuncSetAttribute(hgemm<128,128,64,32,0,false>,
                             cudaFuncAttributeMaxDynamicSharedMemorySize, SMEM_H128x128);
        cudaFuncSetAttribute(hgemm<128,128,64,32,1,false>,
                             cudaFuncAttributeMaxDynamicSharedMemorySize, SMEM_H128x128);
        cudaFuncSetAttribute(hgemm<128,128,64,32,2,false>,
                             cudaFuncAttributeMaxDynamicSharedMemorySize, SMEM_H128x128);
        cudaFuncSetAttribute(hgemm<128,64,32,32,0,false>,
                             cudaFuncAttributeMaxDynamicSharedMemorySize, SMEM_H128x64);
        cudaFuncSetAttribute(hgemm<128,64,32,32,4,false>,
                             cudaFuncAttributeMaxDynamicSharedMemorySize, SMEM_H128x64);
        cudaFuncSetAttribute(score_pt_softmax,
                             cudaFuncAttributeMaxDynamicSharedMemorySize, SMEM_SS);
        attrs_done = true;
    }

    // one-time conversions / pt build
    add2h_kernel<<<PT_ELEMS/4/256, 256>>>((const float4*)pos, (const float4*)typ,
                                          PTh, PT_ELEMS/4);
    ptT_kernel<<<LSEQ, 256>>>(PTh, PTt);
    f2h_kernel<<<(NLAY*3*EE*EE/4)/256, 256>>>((const float4*)Wi, Wih, NLAY*3*EE*EE/4);
    f2h_kernel<<<(NLAY*EE*EE/4)/256,   256>>>((const float4*)Wo, Woh, NLAY*EE*EE/4);
    f2h_kernel<<<(NLAY*DFF*EE/4)/256,  256>>>((const float4*)W1, W1h, NLAY*DFF*EE/4);
    f2h_kernel<<<(NLAY*EE*DFF/4)/256,  256>>>((const float4*)W2, W2h, NLAY*EE*DFF/4);
    f2h_kernel<<<(MROWS*EE/4)/256,     256>>>((const float4*)src, Xh, MROWS*EE/4);

    const float* x = src;     // exact residual input
    for (int l = 0; l < NLAY; l++) {
        // 1) QKV GEMM + fused split epilogue -> Q|K [bh,l,d], V [bh,d,s]
        hgemm<128,128,64,32,3,false><<<dim3(24,32,1), 256, SMEM_H128x128>>>(
            Xh, EE, 0, Wih + (size_t)l*3*EE*EE, EE, 0,
            nullptr, 0, 0, bi + (size_t)l*3*EE, QKVh, MROWS, 3*EE, EE);

        // 2) S = Q @ K^T  (batched over bh)
        hgemm<128,128,64,32,0,false><<<dim3(4,4,BHN), 256, SMEM_H128x128>>>(
            Q, HD, (long long)LSEQ*HD, K, HD, (long long)LSEQ*HD,
            S, LSEQ, (long long)LSEQ*LSEQ, nullptr, nullptr, LSEQ, LSEQ, HD);

        // 3+4) fused: Wh = softmax(S + Q @ PT^T) per row
        score_pt_softmax<<<dim3(2, LSEQ), 512, SMEM_SS>>>(Q, PTh, S, Wh);

        // 5) AO = Wh @ Vt^T (batched over bh)
        hgemm<128,64,32,32,0,false><<<dim3(1,4,BHN), 256, SMEM_H128x64>>>(
            Wh, LSEQ, (long long)LSEQ*LSEQ, Vt, LSEQ, (long long)HD*LSEQ,
            AO, HD, (long long)LSEQ*HD, nullptr, nullptr, LSEQ, HD, LSEQ);

        // 6) AL[l,b,e] = half(AO + Wh[:,l,:] @ PTt[l]^T), fused reorder
        hgemm<128,64,32,32,4,false><<<dim3(1,1,LSEQ), 256, SMEM_H128x64>>>(
            Wh, LSEQ*LSEQ, (long long)LSEQ,
            PTt, LSEQ, (long long)HD*LSEQ,
            AO, LSEQ*HD, (long long)HD,
            nullptr, AL, BHN, HD, LSEQ);

        // 7) Y = AL @ Wo^T + bo
        hgemm<128,128,64,32,1,false><<<dim3(8,32,1), 256, SMEM_H128x128>>>(
            AL, EE, 0, Woh + (size_t)l*EE*EE, EE, 0,
            Y, EE, 0, bo + (size_t)l*EE, nullptr, MROWS, EE, EE);

        // 8) X1 = LN(x + Y)  (exact) + X1h (half)
        ln_res_kernel<<<MROWS, 256>>>(x, Y, g1 + (size_t)l*EE, be1 + (size_t)l*EE, X1, X1h);

        // 9) Hh = half(gelu(X1h @ W1^T + b1))
        hgemm<128,128,64,32,2,false><<<dim3(32,32,1), 256, SMEM_H128x128>>>(
            X1h, EE, 0, W1h + (size_t)l*DFF*EE, EE, 0,
            nullptr, DFF, 0, b1 + (size_t)l*DFF, Hh, MROWS, DFF, EE);

        // 10) Y = Hh @ W2^T + b2
        hgemm<128,128,64,32,1,false><<<dim3(8,32,1), 256, SMEM_H128x128>>>(
            Hh, DFF, 0, W2h + (size_t)l*EE*DFF, DFF, 0,
            Y, EE, 0, b2 + (size_t)l*EE, nullptr, MROWS, EE, DFF);

        // 11) next = LN(X1 + Y); last layer -> d_out (exact), else X + half Xh
        float*  xo  = (l == NLAY-1) ? out : X;
        __half* xoh = (l == NLAY-1) ? nullptr : Xh;
        ln_res_kernel<<<MROWS, 256>>>(X1, Y, g2 + (size_t)l*EE, be2 + (size_t)l*EE, xo, xoh);

        x = X;
    }
}

// round 10
// speedup vs baseline: 1.6374x; 1.0124x over previous
#include <cuda_runtime.h>
#include <cuda_fp16.h>
#include <math.h>
#include <stdint.h>

// ---------------- problem constants ----------------
#define LSEQ 512
#define BB   8
#define EE   1024
#define HH   16
#define HD   64
#define NLAY 2
#define DFF  4096
#define MROWS (LSEQ*BB)          // 4096
#define BHN  (BB*HH)             // 128
#define QSZ  ((size_t)BHN*LSEQ*HD)
#define PT_ELEMS ((size_t)LSEQ*LSEQ*HD)

// ---------------- scratch (device globals, uint4 for 16B alignment) ----------------
__device__ uint4  g_PTh [PT_ELEMS/8];                 // pos+typ half [l,s,d]
__device__ uint4  g_PTt [PT_ELEMS/8];                 // pos+typ half [l,d,s]
__device__ uint4  g_QKVh[3*QSZ/8];                    // Q|K half [bh,l,d]; V half [bh,d,s]
__device__ uint4  g_Sh  [(size_t)BHN*LSEQ*LSEQ/8];    // scores HALF [bh,l,s]
__device__ uint4  g_Wh  [(size_t)BHN*LSEQ*LSEQ/8];    // softmax weights half [bh,l,s]
__device__ uint4  g_AOh [(size_t)BHN*LSEQ*HD/8];      // attn out HALF [bh,l,d]
__device__ uint4  g_ALh [(size_t)MROWS*EE/8];         // attn out half [l,b,e]
__device__ float4 g_Y4  [(size_t)MROWS*EE/4];
__device__ float4 g_X14 [(size_t)MROWS*EE/4];         // exact LN1 out
__device__ uint4  g_X1h [(size_t)MROWS*EE/8];         // half LN1 out
__device__ float4 g_X4  [(size_t)MROWS*EE/4];         // exact layer out
__device__ uint4  g_Xh  [(size_t)MROWS*EE/8];         // half layer in
__device__ uint4  g_Hh  [(size_t)MROWS*DFF/8];        // ffn hidden half
// half weights
__device__ uint4  g_Wih [(size_t)NLAY*3*EE*EE/8];
__device__ uint4  g_Woh [(size_t)NLAY*EE*EE/8];
__device__ uint4  g_W1h [(size_t)NLAY*DFF*EE/8];
__device__ uint4  g_W2h [(size_t)NLAY*EE*DFF/8];

__device__ __forceinline__ float gelu_exact(float x) {
    return 0.5f * x * (1.0f + erff(x * 0.70710678118654752f));
}

__device__ __forceinline__ void cp16(uint32_t saddr, const void* gaddr) {
    asm volatile("cp.async.cg.shared.global [%0], [%1], 16;\n"
                 :: "r"(saddr), "l"(gaddr));
}
__device__ __forceinline__ void cp_commit() {
    asm volatile("cp.async.commit_group;\n");
}
template<int N>
__device__ __forceinline__ void cp_wait() {
    asm volatile("cp.async.wait_group %0;\n" :: "n"(N));
}
__device__ __forceinline__ uint32_t smem_u32(const void* p) {
    uint32_t a;
    asm("{ .reg .u64 t; cvta.to.shared.u64 t, %1; cvt.u32.u64 %0, t; }"
        : "=r"(a) : "l"(p));
    return a;
}
__device__ __forceinline__ void ldsm_x4(uint32_t& r0, uint32_t& r1,
                                        uint32_t& r2, uint32_t& r3, uint32_t saddr)
{
    asm volatile("ldmatrix.sync.aligned.m8n8.x4.shared.b16 {%0,%1,%2,%3}, [%4];"
                 : "=r"(r0), "=r"(r1), "=r"(r2), "=r"(r3) : "r"(saddr));
}
__device__ __forceinline__ void mma_16816(float* acc, const uint32_t* a, const uint32_t* b)
{
    asm volatile(
        "mma.sync.aligned.m16n8k16.row.col.f32.f16.f16.f32 "
        "{%0,%1,%2,%3}, {%4,%5,%6,%7}, {%8,%9}, {%0,%1,%2,%3};\n"
        : "+f"(acc[0]), "+f"(acc[1]), "+f"(acc[2]), "+f"(acc[3])
        : "r"(a[0]), "r"(a[1]), "r"(a[2]), "r"(a[3]), "r"(b[0]), "r"(b[1]));
}

// ---------------- FP16 tensor-core GEMM (NT), cp.async 3-stage + ldmatrix ----------------
// C[M,N] (+)= A[M,K] * B[N,K]^T, fp32 accumulate.
// EPI: 0 plain fp32 C (ACCUM optional); 1 +bias -> fp32 C;
//      2 +bias, gelu -> half auxh[r*ldc+col];
//      3 qkv split: +bias, (q*0.125), half -> Q|K [bh,l,d], V -> [bh,d,s] in auxh;
//      4 read HALF from C (AO half), add, half -> auxh[(l*BB+b)*EE + h*HD + col];
//      5 plain half store into C-as-half at r*ldc + col (sCz given in FLOAT units).
template<int BM, int BN, int WM, int WN, int EPI, bool ACCUM>
__global__ void __launch_bounds__((BM/WM)*(BN/WN)*32, 2)
hgemm(const __half* __restrict__ A, int lda, long long sAz,
      const __half* __restrict__ B, int ldb, long long sBz,
      float* __restrict__ C, int ldc, long long sCz,
      const float* __restrict__ bias, __half* __restrict__ auxh,
      int M, int N, int K)
{
    constexpr int BK = 32;
    constexpr int WARPS_M = BM / WM;
    constexpr int WARPS_N = BN / WN;
    constexpr int THREADS = WARPS_M * WARPS_N * 32;
    constexpr int LDSA = BK + 8;            // 40 halves; ldmatrix conflict-free
    constexpr int A_HALVES = BM * LDSA;
    constexpr int B_HALVES = BN * LDSA;
    constexpr int STAGE_HALVES = A_HALVES + B_HALVES;
    constexpr int NSTAGE = 3;
    constexpr int MI = WM / 16;
    constexpr int NI = WN / 8;

    extern __shared__ __half smem[];

    A += (long long)blockIdx.z * sAz;
    B += (long long)blockIdx.z * sBz;
    C += (long long)blockIdx.z * sCz;

    const int bm = blockIdx.y * BM;
    const int bn = blockIdx.x * BN;
    const int tid  = threadIdx.x;
    const int wid  = tid >> 5;
    const int lane = tid & 31;
    const int wm = (wid / WARPS_N) * WM;
    const int wn = (wid % WARPS_N) * WN;
    const int g = lane >> 2;
    const int c = lane & 3;

    uint32_t smem_base = smem_u32(smem);

    const int a_row = (lane & 15);
    const int a_kof = (lane >> 4) << 3;
    const int b_row = ((lane >> 4) << 3) + (lane & 7);
    const int b_kof = ((lane >> 3) & 1) << 3;

    float acc[MI][NI][4];
    #pragma unroll
    for (int mi = 0; mi < MI; mi++)
        #pragma unroll
        for (int ni = 0; ni < NI; ni++)
            #pragma unroll
            for (int r = 0; r < 4; r++) acc[mi][ni][r] = 0.f;

    const int nIter = K / BK;

    auto load_tiles = [&](int stage, int k0) {
        uint32_t sA = smem_base + (uint32_t)(stage * STAGE_HALVES) * 2u;
        uint32_t sB = sA + (uint32_t)A_HALVES * 2u;
        #pragma unroll
        for (int i = tid; i < BM * (BK/8); i += THREADS) {
            int row = i / (BK/8);
            int kc  = (i % (BK/8)) * 8;
            cp16(sA + (uint32_t)(row * LDSA + kc) * 2u,
                 A + (size_t)(bm + row) * lda + k0 + kc);
        }
        #pragma unroll
        for (int i = tid; i < BN * (BK/8); i += THREADS) {
            int row = i / (BK/8);
            int kc  = (i % (BK/8)) * 8;
            cp16(sB + (uint32_t)(row * LDSA + kc) * 2u,
                 B + (size_t)(bn + row) * ldb + k0 + kc);
        }
        cp_commit();
    };

    load_tiles(0, 0);
    if (nIter > 1) load_tiles(1, BK);

    for (int it = 0; it < nIter; it++) {
        if (it + 2 < nIter) { cp_wait<1>(); } else { cp_wait<0>(); }
        __syncthreads();
        if (it + 2 < nIter) load_tiles((it + 2) % NSTAGE, (it + 2) * BK);

        const uint32_t sAb = smem_base + (uint32_t)((it % NSTAGE) * STAGE_HALVES) * 2u;
        const uint32_t sBb = sAb + (uint32_t)A_HALVES * 2u;

        #pragma unroll
        for (int kk = 0; kk < BK; kk += 16) {
            uint32_t af[MI][4], bf[NI][2];
            #pragma unroll
            for (int mi = 0; mi < MI; mi++) {
                uint32_t addr = sAb + (uint32_t)((wm + mi*16 + a_row) * LDSA
                                                 + kk + a_kof) * 2u;
                ldsm_x4(af[mi][0], af[mi][1], af[mi][2], af[mi][3], addr);
            }
            #pragma unroll
            for (int p = 0; p < NI/2; p++) {
                uint32_t addr = sBb + (uint32_t)((wn + p*16 + b_row) * LDSA
                                                 + kk + b_kof) * 2u;
                ldsm_x4(bf[2*p][0], bf[2*p][1], bf[2*p+1][0], bf[2*p+1][1], addr);
            }
            #pragma unroll
            for (int mi = 0; mi < MI; mi++)
                #pragma unroll
                for (int ni = 0; ni < NI; ni++)
                    mma_16816(acc[mi][ni], af[mi], bf[ni]);
        }
    }

    // ---- epilogue ----
    #pragma unroll
    for (int mi = 0; mi < MI; mi++) {
        #pragma unroll
        for (int ni = 0; ni < NI; ni++) {
            int row = bm + wm + mi*16 + g;
            int col = bn + wn + ni*8 + 2*c;
            float bx = 0.f, by = 0.f;
            if (EPI == 1 || EPI == 2 || EPI == 3) { bx = bias[col]; by = bias[col+1]; }
            #pragma unroll
            for (int half_ = 0; half_ < 2; half_++) {
                int r = row + half_*8;
                float vx = acc[mi][ni][half_*2+0];
                float vy = acc[mi][ni][half_*2+1];
                if (EPI == 1 || EPI == 2 || EPI == 3) { vx += bx; vy += by; }
                if (EPI == 2) {
                    *(__half2*)(auxh + (size_t)r * ldc + col)
                        = __floats2half2_rn(gelu_exact(vx), gelu_exact(vy));
                    continue;
                }
                if (EPI == 3) {
                    int l = r >> 3, b = r & 7;
                    int which = col >> 10;
                    int e = col & 1023;
                    int h = e >> 6, d = e & 63;
                    int bh = b * HH + h;
                    if (which == 0) { vx *= 0.125f; vy *= 0.125f; }
                    if (which < 2) {
                        __half2* P = (__half2*)(auxh + (size_t)which * QSZ
                                                + ((size_t)bh * LSEQ + l) * HD + d);
                        *P = __floats2half2_rn(vx, vy);
                    } else {
                        __half* Pv = auxh + 2 * QSZ + ((size_t)bh * HD + d) * LSEQ + l;
                        Pv[0]    = __float2half_rn(vx);
                        Pv[LSEQ] = __float2half_rn(vy);
                    }
                    continue;
                }
                if (EPI == 4) {
                    // AO is half: C is reinterpreted as __half*
                    __half2 o2 = *(const __half2*)((const __half*)C
                                                   + (size_t)r * ldc + col);
                    float2 o = __half22float2(o2);
                    int l = blockIdx.z;
                    int b = r >> 4, h = r & 15;   // r = bh
                    __half2* P = (__half2*)(auxh + ((size_t)(l * BB + b) * EE)
                                            + h * HD + col);
                    *P = __floats2half2_rn(vx + o.x, vy + o.y);
                    continue;
                }
                if (EPI == 5) {
                    __half* Ch = (__half*)C;
                    *(__half2*)(Ch + (size_t)r * ldc + col)
                        = __floats2half2_rn(vx, vy);
                    continue;
                }
                float2* Cp = (float2*)(C + (size_t)r * ldc + col);
                if (ACCUM) {
                    float2 o = *Cp;
                    vx += o.x; vy += o.y;
                }
                *Cp = make_float2(vx, vy);
            }
        }
    }
}

// ============ fused pt-score accumulate + softmax ============
// One block = (64 bh rows) x (all 512 s cols) for a fixed l.
// acc = Q[bh,l,:] @ PT[l]^T;  then += S (QK^T, half); softmax rows; write Wh half.
// grid (2, LSEQ), block 512 (16 warps, WM=32, WN=64).
__global__ void __launch_bounds__(512, 1)
score_pt_softmax(const __half* __restrict__ Qm, const __half* __restrict__ PT,
                 const __half* __restrict__ S, __half* __restrict__ W)
{
    constexpr int BM = 64, BN = 512, BK = 32, LDSA = 40;
    constexpr int A_HALVES = BM * LDSA;       // 2560
    constexpr int B_HALVES = BN * LDSA;       // 20480
    constexpr int STAGE = A_HALVES + B_HALVES;
    constexpr int MI = 2, NI = 8, WARPS_N = 8;

    extern __shared__ __half smem[];
    __shared__ float redmx[BM][WARPS_N];
    __shared__ float redsm[BM][WARPS_N];

    const int l  = blockIdx.y;
    const int bm = blockIdx.x * BM;
    const int tid  = threadIdx.x;
    const int wid  = tid >> 5;
    const int lane = tid & 31;
    const int wm = (wid / WARPS_N) * 32;
    const int wn = (wid % WARPS_N) * 64;
    const int wnx = wid % WARPS_N;
    const int g = lane >> 2, c = lane & 3;

    uint32_t smem_base = smem_u32(smem);
    const int a_row = (lane & 15);
    const int a_kof = (lane >> 4) << 3;
    const int b_row = ((lane >> 4) << 3) + (lane & 7);
    const int b_kof = ((lane >> 3) & 1) << 3;

    auto load_tiles = [&](int stage, int k0) {
        uint32_t sA = smem_base + (uint32_t)(stage * STAGE) * 2u;
        uint32_t sB = sA + (uint32_t)A_HALVES * 2u;
        #pragma unroll
        for (int i = tid; i < BM * (BK/8); i += 512) {
            int row = i >> 2; int kc = (i & 3) * 8;
            cp16(sA + (uint32_t)(row * LDSA + kc) * 2u,
                 Qm + ((size_t)(bm + row) * LSEQ + l) * HD + k0 + kc);
        }
        #pragma unroll
        for (int i = tid; i < BN * (BK/8); i += 512) {
            int row = i >> 2; int kc = (i & 3) * 8;
            cp16(sB + (uint32_t)(row * LDSA + kc) * 2u,
                 PT + ((size_t)l * LSEQ + row) * HD + k0 + kc);
        }
        cp_commit();
    };

    float acc[MI][NI][4];
    #pragma unroll
    for (int mi = 0; mi < MI; mi++)
        #pragma unroll
        for (int ni = 0; ni < NI; ni++)
            #pragma unroll
            for (int r = 0; r < 4; r++) acc[mi][ni][r] = 0.f;

    load_tiles(0, 0);
    load_tiles(1, BK);

    #pragma unroll
    for (int it = 0; it < 2; it++) {
        if (it == 0) { cp_wait<1>(); } else { cp_wait<0>(); }
        __syncthreads();
        const uint32_t sAb = smem_base + (uint32_t)(it * STAGE) * 2u;
        const uint32_t sBb = sAb + (uint32_t)A_HALVES * 2u;
        #pragma unroll
        for (int kk = 0; kk < BK; kk += 16) {
            uint32_t af[MI][4], bf[NI][2];
            #pragma unroll
            for (int mi = 0; mi < MI; mi++) {
                uint32_t addr = sAb + (uint32_t)((wm + mi*16 + a_row) * LDSA
                                                 + kk + a_kof) * 2u;
                ldsm_x4(af[mi][0], af[mi][1], af[mi][2], af[mi][3], addr);
            }
            #pragma unroll
            for (int p = 0; p < NI/2; p++) {
                uint32_t addr = sBb + (uint32_t)((wn + p*16 + b_row) * LDSA
                                                 + kk + b_kof) * 2u;
                ldsm_x4(bf[2*p][0], bf[2*p][1], bf[2*p+1][0], bf[2*p+1][1], addr);
            }
            #pragma unroll
            for (int mi = 0; mi < MI; mi++)
                #pragma unroll
                for (int ni = 0; ni < NI; ni++)
                    mma_16816(acc[mi][ni], af[mi], bf[ni]);
        }
    }

    // ---- add S (QK^T, half) ----
    #pragma unroll
    for (int mi = 0; mi < MI; mi++)
        #pragma unroll
        for (int half_ = 0; half_ < 2; half_++) {
            int rl = wm + mi*16 + g + half_*8;
            const __half* Sp = S + ((size_t)(bm + rl) * LSEQ + l) * LSEQ;
            #pragma unroll
            for (int ni = 0; ni < NI; ni++) {
                float2 o = __half22float2(
                    *(const __half2*)(Sp + wn + ni*8 + 2*c));
                acc[mi][ni][half_*2+0] += o.x;
                acc[mi][ni][half_*2+1] += o.y;
            }
        }

    // ---- row max ----
    #pragma unroll
    for (int mi = 0; mi < MI; mi++)
        #pragma unroll
        for (int half_ = 0; half_ < 2; half_++) {
            float m = -1e30f;
            #pragma unroll
            for (int ni = 0; ni < NI; ni++) {
                m = fmaxf(m, acc[mi][ni][half_*2+0]);
                m = fmaxf(m, acc[mi][ni][half_*2+1]);
            }
            m = fmaxf(m, __shfl_xor_sync(0xffffffffu, m, 1));
            m = fmaxf(m, __shfl_xor_sync(0xffffffffu, m, 2));
            if (c == 0) redmx[wm + mi*16 + g + half_*8][wnx] = m;
        }
    __syncthreads();

    // ---- exp + row sum ----
    #pragma unroll
    for (int mi = 0; mi < MI; mi++)
        #pragma unroll
        for (int half_ = 0; half_ < 2; half_++) {
            int rl = wm + mi*16 + g + half_*8;
            float m = redmx[rl][0];
            #pragma unroll
            for (int w = 1; w < WARPS_N; w++) m = fmaxf(m, redmx[rl][w]);
            float s = 0.f;
            #pragma unroll
            for (int ni = 0; ni < NI; ni++) {
                float vx = __expf(acc[mi][ni][half_*2+0] - m);
                float vy = __expf(acc[mi][ni][half_*2+1] - m);
                acc[mi][ni][half_*2+0] = vx;
                acc[mi][ni][half_*2+1] = vy;
                s += vx + vy;
            }
            s += __shfl_xor_sync(0xffffffffu, s, 1);
            s += __shfl_xor_sync(0xffffffffu, s, 2);
            if (c == 0) redsm[rl][wnx] = s;
        }
    __syncthreads();

    // ---- scale + write half ----
    #pragma unroll
    for (int mi = 0; mi < MI; mi++)
        #pragma unroll
        for (int half_ = 0; half_ < 2; half_++) {
            int rl = wm + mi*16 + g + half_*8;
            float s = 0.f;
            #pragma unroll
            for (int w = 0; w < WARPS_N; w++) s += redsm[rl][w];
            float inv = 1.0f / s;
            __half* Wp = W + ((size_t)(bm + rl) * LSEQ + l) * LSEQ;
            #pragma unroll
            for (int ni = 0; ni < NI; ni++) {
                *(__half2*)(Wp + wn + ni*8 + 2*c) =
                    __floats2half2_rn(acc[mi][ni][half_*2+0] * inv,
                                      acc[mi][ni][half_*2+1] * inv);
            }
        }
}

// ---------------- pt = half(pos + typ), [l,s,d] ----------------
__global__ void add2h_kernel(const float4* __restrict__ a, const float4* __restrict__ b,
                             __half* __restrict__ o, int n4)
{
    int i = blockIdx.x * blockDim.x + threadIdx.x;
    if (i < n4) {
        float4 x = a[i], y = b[i];
        __half2* p = (__half2*)(o + (size_t)i * 4);
        p[0] = __floats2half2_rn(x.x + y.x, x.y + y.y);
        p[1] = __floats2half2_rn(x.z + y.z, x.w + y.w);
    }
}

// ---------------- fp32 -> half ----------------
__global__ void f2h_kernel(const float4* __restrict__ a, __half* __restrict__ o, int n4)
{
    int i = blockIdx.x * blockDim.x + threadIdx.x;
    if (i < n4) {
        float4 x = a[i];
        __half2* p = (__half2*)(o + (size_t)i * 4);
        p[0] = __floats2half2_rn(x.x, x.y);
        p[1] = __floats2half2_rn(x.z, x.w);
    }
}

// ---------------- transpose PTh [l,s,d] -> PTt [l,d,s] ----------------
__global__ void ptT_kernel(const __half* __restrict__ PTh, __half* __restrict__ PTt)
{
    __shared__ __half tile[64][72];
    int l = blockIdx.x;
    int t = threadIdx.x;   // 256
    for (int st = 0; st < 8; st++) {
        for (int i = t; i < 64 * 8; i += 256) {
            int s = i >> 3, ch = i & 7;
            uint4 v = *(const uint4*)(PTh + ((size_t)l * LSEQ + st*64 + s) * HD + ch*8);
            *(uint4*)&tile[s][ch*8] = v;
        }
        __syncthreads();
        for (int i = t; i < 64 * 32; i += 256) {
            int d = i >> 5;
            int s2 = (i & 31) * 2;
            __half2 h = __halves2half2(tile[s2][d], tile[s2+1][d]);
            *(__half2*)(PTt + ((size_t)l * HD + d) * LSEQ + st*64 + s2) = h;
        }
        __syncthreads();
    }
}

// ---------------- LN(residual); exact fp32 out + optional half copy ----------------
__global__ void ln_res_kernel(const float* __restrict__ X, const float* __restrict__ Y,
                              const float* __restrict__ g, const float* __restrict__ be,
                              float* __restrict__ O, __half* __restrict__ Oh)
{
    int row = blockIdx.x;
    int t = threadIdx.x;
    const float4* x4 = (const float4*)(X + (size_t)row * EE);
    const float4* y4 = (const float4*)(Y + (size_t)row * EE);
    float4 a = x4[t], b = y4[t];
    float4 v = make_float4(a.x+b.x, a.y+b.y, a.z+b.z, a.w+b.w);
    float s = v.x + v.y + v.z + v.w;
    float q = v.x*v.x + v.y*v.y + v.z*v.z + v.w*v.w;
    __shared__ float sh_s[8], sh_q[8];
    #pragma unroll
    for (int o = 16; o; o >>= 1) {
        s += __shfl_xor_sync(0xffffffffu, s, o);
        q += __shfl_xor_sync(0xffffffffu, q, o);
    }
    int wid = t >> 5, lane = t & 31;
    if (!lane) { sh_s[wid] = s; sh_q[wid] = q; }
    __syncthreads();
    if (t < 32) {
        s = (lane < 8) ? sh_s[lane] : 0.f;
        q = (lane < 8) ? sh_q[lane] : 0.f;
        #pragma unroll
        for (int o = 4; o; o >>= 1) {
            s += __shfl_xor_sync(0xffffffffu, s, o);
            q += __shfl_xor_sync(0xffffffffu, q, o);
        }
        if (!lane) { sh_s[0] = s; sh_q[0] = q; }
    }
    __syncthreads();
    float mean = sh_s[0] * (1.f/EE);
    float var  = sh_q[0] * (1.f/EE) - mean * mean;
    float r = rsqrtf(var + 1e-5f);
    float4 gg = ((const float4*)g)[t];
    float4 bb = ((const float4*)be)[t];
    float4 o;
    o.x = (v.x - mean) * r * gg.x + bb.x;
    o.y = (v.y - mean) * r * gg.y + bb.y;
    o.z = (v.z - mean) * r * gg.z + bb.z;
    o.w = (v.w - mean) * r * gg.w + bb.w;
    ((float4*)(O + (size_t)row * EE))[t] = o;
    if (Oh) {
        __half2* p = (__half2*)(Oh + (size_t)row * EE + t * 4);
        p[0] = __floats2half2_rn(o.x, o.y);
        p[1] = __floats2half2_rn(o.z, o.w);
    }
}

// ---------------- launch ----------------
static void* symv(const void* devSymbol) {
    void* p = nullptr;
    cudaGetSymbolAddress(&p, devSymbol);
    return p;
}

#define SMEM_H128x128 (3 * (128*40 + 128*40) * 2)   // 61440
#define SMEM_H128x64  (3 * (128*40 +  64*40) * 2)   // 46080
#define SMEM_SS       (2 * (64*40 + 512*40) * 2)    // 92160

extern "C" void kernel_launch(void* const* d_in, const int* in_sizes, int n_in,
                              void* d_out, int out_size)
{
    const float* src = (const float*)d_in[0];
    const float* pos = (const float*)d_in[1];
    const float* typ = (const float*)d_in[2];
    const float* Wi  = (const float*)d_in[3];
    const float* bi  = (const float*)d_in[4];
    const float* Wo  = (const float*)d_in[5];
    const float* bo  = (const float*)d_in[6];
    const float* W1  = (const float*)d_in[7];
    const float* b1  = (const float*)d_in[8];
    const float* W2  = (const float*)d_in[9];
    const float* b2  = (const float*)d_in[10];
    const float* g1  = (const float*)d_in[11];
    const float* be1 = (const float*)d_in[12];
    const float* g2  = (const float*)d_in[13];
    const float* be2 = (const float*)d_in[14];
    float* out = (float*)d_out;

    __half* PTh  = (__half*)symv(g_PTh);
    __half* PTt  = (__half*)symv(g_PTt);
    __half* QKVh = (__half*)symv(g_QKVh);
    __half* Q = QKVh, *K = QKVh + QSZ, *Vt = QKVh + 2*QSZ;
    __half* Sh   = (__half*)symv(g_Sh);
    __half* Wh   = (__half*)symv(g_Wh);
    __half* AOh  = (__half*)symv(g_AOh);
    __half* AL   = (__half*)symv(g_ALh);
    float*  Y    = (float*)symv(g_Y4);
    float*  X1   = (float*)symv(g_X14);
    __half* X1h  = (__half*)symv(g_X1h);
    float*  X    = (float*)symv(g_X4);
    __half* Xh   = (__half*)symv(g_Xh);
    __half* Hh   = (__half*)symv(g_Hh);
    __half* Wih  = (__half*)symv(g_Wih);
    __half* Woh  = (__half*)symv(g_Woh);
    __half* W1h  = (__half*)symv(g_W1h);
    __half* W2h  = (__half*)symv(g_W2h);

    static bool attrs_done = false;
    if (!attrs_done) {
        cudaFuncSetAttribute(hgemm<128,128,64,32,3,false>,
                             cudaFuncAttributeMaxDynamicSharedMemorySize, SMEM_H128x128);
        cudaFuncSetAttribute(hgemm<128,128,64,32,5,false>,
                             cudaFuncAttributeMaxDynamicSharedMemorySize, SMEM_H128x128);
        cudaFuncSetAttribute(hgemm<128,128,64,32,1,false>,
                             cudaFuncAttributeMaxDynamicSharedMemorySize, SMEM_H128x128);
        cudaFuncSetAttribute(hgemm<128,128,64,32,2,false>,
                             cudaFuncAttributeMaxDynamicSharedMemorySize, SMEM_H128x128);
        cudaFuncSetAttribute(hgemm<128,64,32,32,5,false>,
                             cudaFuncAttributeMaxDynamicSharedMemorySize, SMEM_H128x64);
        cudaFuncSetAttribute(hgemm<128,64,32,32,4,false>,
                             cudaFuncAttributeMaxDynamicSharedMemorySize, SMEM_H128x64);
        cudaFuncSetAttribute(score_pt_softmax,
                             cudaFuncAttributeMaxDynamicSharedMemorySize, SMEM_SS);
        attrs_done = true;
    }

    // one-time conversions / pt build
    add2h_kernel<<<PT_ELEMS/4/256, 256>>>((const float4*)pos, (const float4*)typ,
                                          PTh, PT_ELEMS/4);
    ptT_kernel<<<LSEQ, 256>>>(PTh, PTt);
    f2h_kernel<<<(NLAY*3*EE*EE/4)/256, 256>>>((const float4*)Wi, Wih, NLAY*3*EE*EE/4);
    f2h_kernel<<<(NLAY*EE*EE/4)/256,   256>>>((const float4*)Wo, Woh, NLAY*EE*EE/4);
    f2h_kernel<<<(NLAY*DFF*EE/4)/256,  256>>>((const float4*)W1, W1h, NLAY*DFF*EE/4);
    f2h_kernel<<<(NLAY*EE*DFF/4)/256,  256>>>((const float4*)W2, W2h, NLAY*EE*DFF/4);
    f2h_kernel<<<(MROWS*EE/4)/256,     256>>>((const float4*)src, Xh, MROWS*EE/4);

    const float* x = src;     // exact residual input
    for (int l = 0; l < NLAY; l++) {
        // 1) QKV GEMM + fused split epilogue -> Q|K [bh,l,d], V [bh,d,s]
        hgemm<128,128,64,32,3,false><<<dim3(24,32,1), 256, SMEM_H128x128>>>(
            Xh, EE, 0, Wih + (size_t)l*3*EE*EE, EE, 0,
            nullptr, 0, 0, bi + (size_t)l*3*EE, QKVh, MROWS, 3*EE, EE);

        // 2) Sh = half(Q @ K^T)  (batched over bh) — EPI5, sCz in FLOAT units
        hgemm<128,128,64,32,5,false><<<dim3(4,4,BHN), 256, SMEM_H128x128>>>(
            Q, HD, (long long)LSEQ*HD, K, HD, (long long)LSEQ*HD,
            (float*)Sh, LSEQ, (long long)LSEQ*LSEQ/2, nullptr, nullptr,
            LSEQ, LSEQ, HD);

        // 3+4) fused: Wh = softmax(Sh + Q @ PT^T) per row
        score_pt_softmax<<<dim3(2, LSEQ), 512, SMEM_SS>>>(Q, PTh, Sh, Wh);

        // 5) AOh = half(Wh @ Vt^T) (batched over bh) — EPI5
        hgemm<128,64,32,32,5,false><<<dim3(1,4,BHN), 256, SMEM_H128x64>>>(
            Wh, LSEQ, (long long)LSEQ*LSEQ, Vt, LSEQ, (long long)HD*LSEQ,
            (float*)AOh, HD, (long long)LSEQ*HD/2, nullptr, nullptr,
            LSEQ, HD, LSEQ);

        // 6) AL[l,b,e] = half(AOh + Wh[:,l,:] @ PTt[l]^T), fused reorder — EPI4
        hgemm<128,64,32,32,4,false><<<dim3(1,1,LSEQ), 256, SMEM_H128x64>>>(
            Wh, LSEQ*LSEQ, (long long)LSEQ,
            PTt, LSEQ, (long long)HD*LSEQ,
            (float*)AOh, LSEQ*HD, (long long)HD/2,
            nullptr, AL, BHN, HD, LSEQ);

        // 7) Y = AL @ Wo^T + bo
        hgemm<128,128,64,32,1,false><<<dim3(8,32,1), 256, SMEM_H128x128>>>(
            AL, EE, 0, Woh + (size_t)l*EE*EE, EE, 0,
            Y, EE, 0, bo + (size_t)l*EE, nullptr, MROWS, EE, EE);

        // 8) X1 = LN(x + Y)  (exact) + X1h (half)
        ln_res_kernel<<<MROWS, 256>>>(x, Y, g1 + (size_t)l*EE, be1 + (size_t)l*EE, X1, X1h);

        // 9) Hh = half(gelu(X1h @ W1^T + b1))
        hgemm<128,128,64,32,2,false><<<dim3(32,32,1), 256, SMEM_H128x128>>>(
            X1h, EE, 0, W1h + (size_t)l*DFF*EE, EE, 0,
            nullptr, DFF, 0, b1 + (size_t)l*DFF, Hh, MROWS, DFF, EE);

        // 10) Y = Hh @ W2^T + b2
        hgemm<128,128,64,32,1,false><<<dim3(8,32,1), 256, SMEM_H128x128>>>(
            Hh, DFF, 0, W2h + (size_t)l*EE*DFF, DFF, 0,
            Y, EE, 0, b2 + (size_t)l*EE, nullptr, MROWS, EE, DFF);

        // 11) next = LN(X1 + Y); last layer -> d_out (exact), else X + half Xh
        float*  xo  = (l == NLAY-1) ? out : X;
        __half* xoh = (l == NLAY-1) ? nullptr : Xh;
        ln_res_kernel<<<MROWS, 256>>>(X1, Y, g2 + (size_t)l*EE, be2 + (size_t)l*EE, xo, xoh);

        x = X;
    }
}